// round 6
// baseline (speedup 1.0000x reference)
#include <cuda_runtime.h>
#include <cuda_bf16.h>
#include <cuda_fp16.h>
#include <cstdint>

#define N_NODES 100000
#define N_EDGES 1600000
#define NFEAT   512
#define NHID    128
#define NCLASS  64
#define SCAN_BLOCKS ((N_NODES + 1023) / 1024)   // 98

// ---------------- device scratch (no allocations allowed) ----------------
struct __align__(8) Edge { int s; float w; };

__device__ float  g_support1[(size_t)N_NODES * NHID];
__device__ __half g_support2h[(size_t)N_NODES * NCLASS];
__device__ int   g_cnt[N_NODES];
__device__ int   g_row_ptr[N_NODES + 1];
__device__ int   g_cursor[N_NODES + 1];
__device__ Edge  g_edges[N_EDGES];
__device__ int   g_idx64;
__device__ int   g_part[SCAN_BLOCKS];
__device__ int   g_partoff[SCAN_BLOCKS];
// pre-split/transposed weights: [n][k] bf16 hi/lo (K-major)
__device__ __align__(16) __nv_bfloat16 g_B1t_h[NHID * NFEAT];
__device__ __align__(16) __nv_bfloat16 g_B1t_l[NHID * NFEAT];
__device__ __align__(16) __nv_bfloat16 g_B2t_h[NCLASS * NHID];
__device__ __align__(16) __nv_bfloat16 g_B2t_l[NCLASS * NHID];

// ---------------- index dtype detection ----------------
__global__ void k_detect(const void* dst) {
    if (threadIdx.x == 0 && blockIdx.x == 0) {
        const unsigned long long* p = (const unsigned long long*)dst;
        int is64 = 1;
        #pragma unroll
        for (int i = 0; i < 8; i++)
            if (p[i] >= (unsigned long long)N_NODES) is64 = 0;
        g_idx64 = is64;
    }
}
__device__ __forceinline__ int load_idx(const void* p, int i, int is64) {
    return is64 ? (int)((const long long*)p)[i] : ((const int*)p)[i];
}

// ---------------- CSR build ----------------
__global__ void k_zero_cnt() {
    int i = blockIdx.x * blockDim.x + threadIdx.x;
    if (i < N_NODES) g_cnt[i] = 0;
}
__global__ void k_count(const void* dst) {
    int e = blockIdx.x * blockDim.x + threadIdx.x;
    if (e < N_EDGES) {
        int is64 = g_idx64;
        atomicAdd(&g_cnt[load_idx(dst, e, is64)], 1);
    }
}
__global__ void k_partsum() {
    int i = blockIdx.x * 1024 + threadIdx.x;
    int x = (i < N_NODES) ? g_cnt[i] : 0;
    #pragma unroll
    for (int o = 16; o > 0; o >>= 1) x += __shfl_xor_sync(0xFFFFFFFFu, x, o);
    __shared__ int ws[32];
    int lane = threadIdx.x & 31, w = threadIdx.x >> 5;
    if (lane == 0) ws[w] = x;
    __syncthreads();
    if (w == 0) {
        int v = ws[lane];
        #pragma unroll
        for (int o = 16; o > 0; o >>= 1) v += __shfl_xor_sync(0xFFFFFFFFu, v, o);
        if (lane == 0) g_part[blockIdx.x] = v;
    }
}
__global__ void k_scanpart() {
    __shared__ int s[128];
    int tid = threadIdx.x;
    int x = (tid < SCAN_BLOCKS) ? g_part[tid] : 0;
    s[tid] = x;
    __syncthreads();
    #pragma unroll
    for (int off = 1; off < 128; off <<= 1) {
        int t = (tid >= off) ? s[tid - off] : 0;
        __syncthreads();
        s[tid] += t;
        __syncthreads();
    }
    if (tid < SCAN_BLOCKS) g_partoff[tid] = s[tid] - x;
    if (tid == 127) g_row_ptr[N_NODES] = s[127];
}
__global__ void k_scanfinal() {
    __shared__ int warp_sums[32];
    int tid = threadIdx.x;
    int lane = tid & 31, w = tid >> 5;
    int i = blockIdx.x * 1024 + tid;
    int x = (i < N_NODES) ? g_cnt[i] : 0;
    int v = x;
    #pragma unroll
    for (int o = 1; o < 32; o <<= 1) {
        int t = __shfl_up_sync(0xFFFFFFFFu, v, o);
        if (lane >= o) v += t;
    }
    if (lane == 31) warp_sums[w] = v;
    __syncthreads();
    if (w == 0) {
        int s = warp_sums[lane];
        #pragma unroll
        for (int o = 1; o < 32; o <<= 1) {
            int t = __shfl_up_sync(0xFFFFFFFFu, s, o);
            if (lane >= o) s += t;
        }
        warp_sums[lane] = s;
    }
    __syncthreads();
    int excl = v - x + ((w == 0) ? 0 : warp_sums[w - 1]);
    if (i < N_NODES) {
        int val = g_partoff[blockIdx.x] + excl;
        g_row_ptr[i] = val;
        g_cursor[i]  = val;
    }
}
__global__ void k_scatter(const void* src, const void* dst,
                          const float* __restrict__ ew) {
    int e = blockIdx.x * blockDim.x + threadIdx.x;
    if (e < N_EDGES) {
        int is64 = g_idx64;
        int d = load_idx(dst, e, is64);
        int pos = atomicAdd(&g_cursor[d], 1);
        Edge ed; ed.s = load_idx(src, e, is64); ed.w = ew[e];
        g_edges[pos] = ed;
    }
}

// ---------------- weight prep: transpose + split into bf16 hi/lo ----------
template <int K, int N>
__global__ void k_prepB(const float* __restrict__ W,
                        __nv_bfloat16* __restrict__ outh,
                        __nv_bfloat16* __restrict__ outl) {
    int t = blockIdx.x * blockDim.x + threadIdx.x;
    if (t < K * N) {
        int n = t / K, k = t % K;
        float v = W[(size_t)k * N + n];
        __nv_bfloat16 h = __float2bfloat16_rn(v);
        outh[t] = h;
        outl[t] = __float2bfloat16_rn(v - __bfloat162float(h));
    }
}

// ---------------- split-bf16 tensor-core GEMM, 2-stage + ldmatrix ---------
__device__ __forceinline__ void mma16816(float* c, const unsigned* a,
                                         const unsigned* b) {
    asm volatile(
        "mma.sync.aligned.m16n8k16.row.col.f32.bf16.bf16.f32 "
        "{%0,%1,%2,%3}, {%4,%5,%6,%7}, {%8,%9}, {%0,%1,%2,%3};\n"
        : "+f"(c[0]), "+f"(c[1]), "+f"(c[2]), "+f"(c[3])
        : "r"(a[0]), "r"(a[1]), "r"(a[2]), "r"(a[3]), "r"(b[0]), "r"(b[1]));
}
#define LDSM_X4(r, a)                                                        \
    asm volatile("ldmatrix.sync.aligned.m8n8.x4.shared.b16 "                 \
                 "{%0,%1,%2,%3}, [%4];"                                      \
                 : "=r"((r)[0]), "=r"((r)[1]), "=r"((r)[2]), "=r"((r)[3])    \
                 : "r"(a))

// C[M,BN] = A[M,K](fp32, split in-kernel) @ Bt(pre-split [n][k] bf16)
// BM=128, BK=32. 8 warps. A double-buffered via register staging + STS,
// B double-buffered via cp.async. smem rows padded to 20 words (40 bf16).
// HALF_OUT: write C as fp16 (__half2 pairs) instead of fp32.
template <int K, int BN, bool HALF_OUT>
__global__ __launch_bounds__(256, 2) void k_mma_gemm(
    const float* __restrict__ A,
    const __nv_bfloat16* __restrict__ Bh,
    const __nv_bfloat16* __restrict__ Bl,
    void* __restrict__ Cv, int M) {
    constexpr int NWN = BN / 32;
    constexpr int NWM = 8 / NWN;
    constexpr int WTM = 128 / NWM;
    constexpr int MT  = WTM / 16;
    constexpr int KT  = K / 32;
    constexpr int A_ST = 128 * 20;   // words per stage (per hi/lo matrix)
    constexpr int B_ST = BN * 20;

    extern __shared__ char smem_raw[];
    unsigned* Ash = (unsigned*)smem_raw;                 // [2][A_ST]
    unsigned* Asl = Ash + 2 * A_ST;
    unsigned* Bsh = Asl + 2 * A_ST;                      // [2][B_ST]
    unsigned* Bsl = Bsh + 2 * B_ST;

    const int tid = threadIdx.x;
    const int wid = tid >> 5, lane = tid & 31;
    const int wm = wid / NWN, wn = wid % NWN;
    const int gid = lane >> 2, t4 = lane & 3;
    const int bm0 = blockIdx.x * 128;

    unsigned sBh = (unsigned)__cvta_generic_to_shared(Bsh);
    unsigned sBl = (unsigned)__cvta_generic_to_shared(Bsl);

    // ---- per-lane ldmatrix base addresses (bytes) ----
    const int rowA = wm * WTM + (lane & 7) + ((lane >> 3) & 1) * 8;
    const int colA = ((lane >> 4) & 1) * 4;
    const unsigned aOff = (unsigned)(rowA * 20 + colA) * 4u;
    const unsigned aAddrH = (unsigned)__cvta_generic_to_shared(Ash) + aOff;
    const unsigned aAddrL = (unsigned)__cvta_generic_to_shared(Asl) + aOff;
    const int rowB = wn * 32 + (lane & 7) + ((lane >> 4) & 1) * 8;
    const int colB = ((lane >> 3) & 1) * 4;
    const unsigned bOff = (unsigned)(rowB * 20 + colB) * 4u;
    const unsigned bAddrH = sBh + bOff;
    const unsigned bAddrL = sBl + bOff;

    // ---- A register staging: 4 float4 per thread per stage ----
    float4 areg[4];
    auto ldgA = [&](int kt) {
        int k0 = kt * 32;
        #pragma unroll
        for (int i = 0; i < 4; i++) {
            int linear = tid + 256 * i;
            int row = linear >> 3, c4 = linear & 7;
            int gr = bm0 + row;
            areg[i] = (gr < M)
                ? *(const float4*)(A + (size_t)gr * K + k0 + c4 * 4)
                : make_float4(0.f, 0.f, 0.f, 0.f);
        }
    };
    auto stsA = [&](int st) {
        #pragma unroll
        for (int i = 0; i < 4; i++) {
            int linear = tid + 256 * i;
            int row = linear >> 3, c4 = linear & 7;
            float f[4] = {areg[i].x, areg[i].y, areg[i].z, areg[i].w};
            unsigned short hh[4], ll[4];
            #pragma unroll
            for (int c = 0; c < 4; c++) {
                __nv_bfloat16 h = __float2bfloat16_rn(f[c]);
                __nv_bfloat16 l = __float2bfloat16_rn(f[c] - __bfloat162float(h));
                hh[c] = __bfloat16_as_ushort(h);
                ll[c] = __bfloat16_as_ushort(l);
            }
            uint2 ph = make_uint2((unsigned)hh[0] | ((unsigned)hh[1] << 16),
                                  (unsigned)hh[2] | ((unsigned)hh[3] << 16));
            uint2 pl = make_uint2((unsigned)ll[0] | ((unsigned)ll[1] << 16),
                                  (unsigned)ll[2] | ((unsigned)ll[3] << 16));
            *(uint2*)&Ash[st * A_ST + row * 20 + c4 * 2] = ph;
            *(uint2*)&Asl[st * A_ST + row * 20 + c4 * 2] = pl;
        }
    };
    auto cpB = [&](int kt, int st) {
        int k0 = kt * 32;
        constexpr int BI = (BN * 4) / 256;
        #pragma unroll
        for (int i = 0; i < BI; i++) {
            int linear = tid + 256 * i;
            int row = linear >> 2, j = linear & 3;
            unsigned dh = sBh + (st * B_ST + row * 20 + j * 4) * 4;
            unsigned dl = sBl + (st * B_ST + row * 20 + j * 4) * 4;
            const __nv_bfloat16* ph = Bh + (size_t)row * K + k0 + j * 8;
            const __nv_bfloat16* pl = Bl + (size_t)row * K + k0 + j * 8;
            asm volatile("cp.async.ca.shared.global [%0], [%1], 16;\n" :: "r"(dh), "l"(ph));
            asm volatile("cp.async.ca.shared.global [%0], [%1], 16;\n" :: "r"(dl), "l"(pl));
        }
        asm volatile("cp.async.commit_group;\n");
    };

    float acc[MT][4][4];
    #pragma unroll
    for (int m = 0; m < MT; m++)
        #pragma unroll
        for (int n = 0; n < 4; n++)
            #pragma unroll
            for (int r = 0; r < 4; r++) acc[m][n][r] = 0.f;

    // prologue: stage 0
    ldgA(0);
    cpB(0, 0);
    stsA(0);

    for (int kt = 0; kt < KT; kt++) {
        const int st = kt & 1;
        if (kt + 1 < KT) {
            ldgA(kt + 1);          // LDG in flight across compute
            cpB(kt + 1, (kt + 1) & 1);
            asm volatile("cp.async.wait_group 1;\n");
        } else {
            asm volatile("cp.async.wait_group 0;\n");
        }
        __syncthreads();           // stage kt (A sts + B cp.async) visible

        const unsigned aStOff = (unsigned)(st * A_ST) * 4u;
        const unsigned bStOff = (unsigned)(st * B_ST) * 4u;
        #pragma unroll
        for (int kk = 0; kk < 2; kk++) {
            const unsigned kOff = (unsigned)(kk * 8) * 4u;
            unsigned bh[2][4], bl[2][4];
            #pragma unroll
            for (int p = 0; p < 2; p++) {
                unsigned po = (unsigned)(p * 16 * 20) * 4u;
                LDSM_X4(bh[p], bAddrH + bStOff + kOff + po);
                LDSM_X4(bl[p], bAddrL + bStOff + kOff + po);
            }
            #pragma unroll
            for (int mt = 0; mt < MT; mt++) {
                unsigned mo = (unsigned)(mt * 16 * 20) * 4u;
                unsigned ah[4], al[4];
                LDSM_X4(ah, aAddrH + aStOff + kOff + mo);
                LDSM_X4(al, aAddrL + aStOff + kOff + mo);
                #pragma unroll
                for (int nt = 0; nt < 4; nt++) {
                    const unsigned* bhp = &bh[nt >> 1][(nt & 1) * 2];
                    const unsigned* blp = &bl[nt >> 1][(nt & 1) * 2];
                    mma16816(acc[mt][nt], ah, bhp);
                    mma16816(acc[mt][nt], ah, blp);
                    mma16816(acc[mt][nt], al, bhp);
                }
            }
        }
        __syncthreads();           // everyone done reading buf st
        if (kt + 1 < KT) stsA((kt + 1) & 1);   // safe: buf (kt+1)&1 free now
    }

    // ---- epilogue ----
    #pragma unroll
    for (int mt = 0; mt < MT; mt++) {
        int r = bm0 + wm * WTM + mt * 16 + gid;
        #pragma unroll
        for (int nt = 0; nt < 4; nt++) {
            int c = wn * 32 + nt * 8 + 2 * t4;
            if (HALF_OUT) {
                __half2* C2 = (__half2*)Cv;
                if (r < M)
                    C2[((size_t)r * BN + c) >> 1] =
                        __floats2half2_rn(acc[mt][nt][0], acc[mt][nt][1]);
                if (r + 8 < M)
                    C2[((size_t)(r + 8) * BN + c) >> 1] =
                        __floats2half2_rn(acc[mt][nt][2], acc[mt][nt][3]);
            } else {
                float* C = (float*)Cv;
                if (r < M)
                    *(float2*)&C[(size_t)r * BN + c] =
                        make_float2(acc[mt][nt][0], acc[mt][nt][1]);
                if (r + 8 < M)
                    *(float2*)&C[(size_t)(r + 8) * BN + c] =
                        make_float2(acc[mt][nt][2], acc[mt][nt][3]);
            }
        }
    }
}

// ---------------- layer-1 aggregation: warp per node, fused bias+leaky ----
__global__ void k_agg1(const float* __restrict__ sup,
                       const float* __restrict__ bias,
                       float* __restrict__ h) {
    int gw = (blockIdx.x * blockDim.x + threadIdx.x) >> 5;
    if (gw >= N_NODES) return;
    int lane = threadIdx.x & 31;
    int beg = g_row_ptr[gw], end = g_row_ptr[gw + 1];
    float4 a0 = make_float4(0.f, 0.f, 0.f, 0.f);
    float4 a1 = make_float4(0.f, 0.f, 0.f, 0.f);
    float4 a2 = make_float4(0.f, 0.f, 0.f, 0.f);
    float4 a3 = make_float4(0.f, 0.f, 0.f, 0.f);
    int e = beg;
    for (; e + 4 <= end; e += 4) {
        Edge e0 = g_edges[e], e1 = g_edges[e + 1];
        Edge e2 = g_edges[e + 2], e3 = g_edges[e + 3];
        float4 v0 = ((const float4*)(sup + (size_t)e0.s * NHID))[lane];
        float4 v1 = ((const float4*)(sup + (size_t)e1.s * NHID))[lane];
        float4 v2 = ((const float4*)(sup + (size_t)e2.s * NHID))[lane];
        float4 v3 = ((const float4*)(sup + (size_t)e3.s * NHID))[lane];
        a0.x += e0.w * v0.x; a0.y += e0.w * v0.y; a0.z += e0.w * v0.z; a0.w += e0.w * v0.w;
        a1.x += e1.w * v1.x; a1.y += e1.w * v1.y; a1.z += e1.w * v1.z; a1.w += e1.w * v1.w;
        a2.x += e2.w * v2.x; a2.y += e2.w * v2.y; a2.z += e2.w * v2.z; a2.w += e2.w * v2.w;
        a3.x += e3.w * v3.x; a3.y += e3.w * v3.y; a3.z += e3.w * v3.z; a3.w += e3.w * v3.w;
    }
    for (; e < end; e++) {
        Edge e0 = g_edges[e];
        float4 v0 = ((const float4*)(sup + (size_t)e0.s * NHID))[lane];
        a0.x += e0.w * v0.x; a0.y += e0.w * v0.y; a0.z += e0.w * v0.z; a0.w += e0.w * v0.w;
    }
    float4 bb = ((const float4*)bias)[lane];
    float4 r;
    r.x = (a0.x + a1.x) + (a2.x + a3.x) + bb.x;
    r.y = (a0.y + a1.y) + (a2.y + a3.y) + bb.y;
    r.z = (a0.z + a1.z) + (a2.z + a3.z) + bb.z;
    r.w = (a0.w + a1.w) + (a2.w + a3.w) + bb.w;
    r.x = r.x > 0.f ? r.x : 0.01f * r.x;
    r.y = r.y > 0.f ? r.y : 0.01f * r.y;
    r.z = r.z > 0.f ? r.z : 0.01f * r.z;
    r.w = r.w > 0.f ? r.w : 0.01f * r.w;
    ((float4*)(h + (size_t)gw * NHID))[lane] = r;
}

// ------- layer-2 aggregation: fp16 sup2, warp per node, bias + softmax ----
__global__ void k_agg2(const __half2* __restrict__ sup2,
                       const float* __restrict__ bias,
                       float* __restrict__ out) {
    int gw = (blockIdx.x * blockDim.x + threadIdx.x) >> 5;
    if (gw >= N_NODES) return;
    int lane = threadIdx.x & 31;
    int beg = g_row_ptr[gw], end = g_row_ptr[gw + 1];
    float2 a0 = make_float2(0.f, 0.f);
    float2 a1 = make_float2(0.f, 0.f);
    float2 a2 = make_float2(0.f, 0.f);
    float2 a3 = make_float2(0.f, 0.f);
    int e = beg;
    for (; e + 4 <= end; e += 4) {
        Edge e0 = g_edges[e], e1 = g_edges[e + 1];
        Edge e2 = g_edges[e + 2], e3 = g_edges[e + 3];
        float2 v0 = __half22float2(sup2[(size_t)e0.s * 32 + lane]);
        float2 v1 = __half22float2(sup2[(size_t)e1.s * 32 + lane]);
        float2 v2 = __half22float2(sup2[(size_t)e2.s * 32 + lane]);
        float2 v3 = __half22float2(sup2[(size_t)e3.s * 32 + lane]);
        a0.x += e0.w * v0.x; a0.y += e0.w * v0.y;
        a1.x += e1.w * v1.x; a1.y += e1.w * v1.y;
        a2.x += e2.w * v2.x; a2.y += e2.w * v2.y;
        a3.x += e3.w * v3.x; a3.y += e3.w * v3.y;
    }
    for (; e < end; e++) {
        Edge e0 = g_edges[e];
        float2 v0 = __half22float2(sup2[(size_t)e0.s * 32 + lane]);
        a0.x += e0.w * v0.x; a0.y += e0.w * v0.y;
    }
    float2 bb = ((const float2*)bias)[lane];
    float lx = (a0.x + a1.x) + (a2.x + a3.x) + bb.x;
    float ly = (a0.y + a1.y) + (a2.y + a3.y) + bb.y;
    float m = fmaxf(lx, ly);
    #pragma unroll
    for (int o = 16; o > 0; o >>= 1)
        m = fmaxf(m, __shfl_xor_sync(0xFFFFFFFFu, m, o));
    float ex = __expf(lx - m), ey = __expf(ly - m);
    float s = ex + ey;
    #pragma unroll
    for (int o = 16; o > 0; o >>= 1)
        s += __shfl_xor_sync(0xFFFFFFFFu, s, o);
    float inv = 1.f / s;
    ((float2*)(out + (size_t)gw * NCLASS))[lane] = make_float2(ex * inv, ey * inv);
}

// ---------------- launch ----------------
extern "C" void kernel_launch(void* const* d_in, const int* in_sizes, int n_in,
                              void* d_out, int out_size) {
    const float* y    = (const float*)d_in[0];
    const void*  srcp = d_in[1];
    const void*  dstp = d_in[2];
    const float* ew   = (const float*)d_in[3];
    const float* W1   = (const float*)d_in[4];
    const float* b1   = (const float*)d_in[5];
    const float* W2   = (const float*)d_in[6];
    const float* b2   = (const float*)d_in[7];

    float* out_softmax = (float*)d_out;                              // [N, 64]
    float* out_emb     = (float*)d_out + (size_t)N_NODES * NCLASS;   // [N, 128]

    float* sup1;   cudaGetSymbolAddress((void**)&sup1, g_support1);
    __half* sup2h; cudaGetSymbolAddress((void**)&sup2h, g_support2h);
    __nv_bfloat16 *b1h, *b1l, *b2h, *b2l;
    cudaGetSymbolAddress((void**)&b1h, g_B1t_h);
    cudaGetSymbolAddress((void**)&b1l, g_B1t_l);
    cudaGetSymbolAddress((void**)&b2h, g_B2t_h);
    cudaGetSymbolAddress((void**)&b2l, g_B2t_l);

    // smem: A hi/lo 2 stages (40960B) + B hi/lo 2 stages
    const int SMEM1 = 40960 + 40960;   // BN=128
    const int SMEM2 = 40960 + 20480;   // BN=64
    static bool init_done = false;
    static cudaStream_t s2 = nullptr;
    static cudaEvent_t evFork = nullptr, evJoin = nullptr;
    if (!init_done) {
        cudaFuncSetAttribute(k_mma_gemm<NFEAT, NHID, false>,
                             cudaFuncAttributeMaxDynamicSharedMemorySize, SMEM1);
        cudaFuncSetAttribute(k_mma_gemm<NHID, NCLASS, true>,
                             cudaFuncAttributeMaxDynamicSharedMemorySize, SMEM2);
        cudaStreamCreateWithFlags(&s2, cudaStreamNonBlocking);
        cudaEventCreateWithFlags(&evFork, cudaEventDisableTiming);
        cudaEventCreateWithFlags(&evJoin, cudaEventDisableTiming);
        init_done = true;
    }

    // ---- fork: CSR build + W2 prep on side stream, hidden under GEMM1 ----
    cudaEventRecord(evFork, 0);
    cudaStreamWaitEvent(s2, evFork, 0);

    k_prepB<NHID, NCLASS><<<(NHID * NCLASS + 255) / 256, 256, 0, s2>>>(W2, b2h, b2l);
    k_detect<<<1, 1, 0, s2>>>(dstp);
    k_zero_cnt<<<(N_NODES + 255) / 256, 256, 0, s2>>>();
    k_count<<<(N_EDGES + 255) / 256, 256, 0, s2>>>(dstp);
    k_partsum<<<SCAN_BLOCKS, 1024, 0, s2>>>();
    k_scanpart<<<1, 128, 0, s2>>>();
    k_scanfinal<<<SCAN_BLOCKS, 1024, 0, s2>>>();
    k_scatter<<<(N_EDGES + 255) / 256, 256, 0, s2>>>(srcp, dstp, ew);
    cudaEventRecord(evJoin, s2);

    // ---- main stream: dense chain ----
    k_prepB<NFEAT, NHID><<<(NFEAT * NHID + 255) / 256, 256>>>(W1, b1h, b1l);

    const int gblocks = (N_NODES + 127) / 128;
    k_mma_gemm<NFEAT, NHID, false><<<gblocks, 256, SMEM1>>>(y, b1h, b1l, sup1,
                                                            N_NODES);

    // ---- join: agg needs CSR ----
    cudaStreamWaitEvent(0, evJoin, 0);

    k_agg1<<<(N_NODES * 32 + 255) / 256, 256>>>(sup1, b1, out_emb);
    k_mma_gemm<NHID, NCLASS, true><<<gblocks, 256, SMEM2>>>(out_emb, b2h, b2l,
                                                            sup2h, N_NODES);
    k_agg2<<<(N_NODES * 32 + 255) / 256, 256>>>((const __half2*)sup2h, b2,
                                                out_softmax);
}

// round 7
// speedup vs baseline: 1.0891x; 1.0891x over previous
#include <cuda_runtime.h>
#include <cuda_bf16.h>
#include <cstdint>

#define N_NODES 100000
#define N_EDGES 1600000
#define NFEAT   512
#define NHID    128
#define NCLASS  64
#define SCAN_BLOCKS ((N_NODES + 1023) / 1024)   // 98

// ---------------- device scratch (no allocations allowed) ----------------
struct __align__(8) Edge { int s; float w; };

__device__ float g_support1[(size_t)N_NODES * NHID];
__device__ float g_support2[(size_t)N_NODES * NCLASS];
__device__ int   g_cnt[N_NODES];
__device__ int   g_row_ptr[N_NODES + 1];
__device__ int   g_cursor[N_NODES + 1];
__device__ Edge  g_edges[N_EDGES];
__device__ int   g_idx64;
__device__ int   g_part[SCAN_BLOCKS];
__device__ int   g_partoff[SCAN_BLOCKS];
// pre-split/transposed weights: [n][k] bf16 hi/lo (K-major)
__device__ __align__(16) __nv_bfloat16 g_B1t_h[NHID * NFEAT];
__device__ __align__(16) __nv_bfloat16 g_B1t_l[NHID * NFEAT];
__device__ __align__(16) __nv_bfloat16 g_B2t_h[NCLASS * NHID];
__device__ __align__(16) __nv_bfloat16 g_B2t_l[NCLASS * NHID];

// ---------------- index dtype detection ----------------
__global__ void k_detect(const void* dst) {
    if (threadIdx.x == 0 && blockIdx.x == 0) {
        const unsigned long long* p = (const unsigned long long*)dst;
        int is64 = 1;
        #pragma unroll
        for (int i = 0; i < 8; i++)
            if (p[i] >= (unsigned long long)N_NODES) is64 = 0;
        g_idx64 = is64;
    }
}
__device__ __forceinline__ int load_idx(const void* p, int i, int is64) {
    return is64 ? (int)((const long long*)p)[i] : ((const int*)p)[i];
}

// ---------------- CSR build ----------------
__global__ void k_zero_cnt() {
    int i = blockIdx.x * blockDim.x + threadIdx.x;
    if (i < N_NODES) g_cnt[i] = 0;
}
__global__ void k_count(const void* dst) {
    int e = blockIdx.x * blockDim.x + threadIdx.x;
    if (e < N_EDGES) {
        int is64 = g_idx64;
        atomicAdd(&g_cnt[load_idx(dst, e, is64)], 1);
    }
}
__global__ void k_partsum() {
    int i = blockIdx.x * 1024 + threadIdx.x;
    int x = (i < N_NODES) ? g_cnt[i] : 0;
    #pragma unroll
    for (int o = 16; o > 0; o >>= 1) x += __shfl_xor_sync(0xFFFFFFFFu, x, o);
    __shared__ int ws[32];
    int lane = threadIdx.x & 31, w = threadIdx.x >> 5;
    if (lane == 0) ws[w] = x;
    __syncthreads();
    if (w == 0) {
        int v = ws[lane];
        #pragma unroll
        for (int o = 16; o > 0; o >>= 1) v += __shfl_xor_sync(0xFFFFFFFFu, v, o);
        if (lane == 0) g_part[blockIdx.x] = v;
    }
}
__global__ void k_scanpart() {
    __shared__ int s[128];
    int tid = threadIdx.x;
    int x = (tid < SCAN_BLOCKS) ? g_part[tid] : 0;
    s[tid] = x;
    __syncthreads();
    #pragma unroll
    for (int off = 1; off < 128; off <<= 1) {
        int t = (tid >= off) ? s[tid - off] : 0;
        __syncthreads();
        s[tid] += t;
        __syncthreads();
    }
    if (tid < SCAN_BLOCKS) g_partoff[tid] = s[tid] - x;
    if (tid == 127) g_row_ptr[N_NODES] = s[127];
}
__global__ void k_scanfinal() {
    __shared__ int warp_sums[32];
    int tid = threadIdx.x;
    int lane = tid & 31, w = tid >> 5;
    int i = blockIdx.x * 1024 + tid;
    int x = (i < N_NODES) ? g_cnt[i] : 0;
    int v = x;
    #pragma unroll
    for (int o = 1; o < 32; o <<= 1) {
        int t = __shfl_up_sync(0xFFFFFFFFu, v, o);
        if (lane >= o) v += t;
    }
    if (lane == 31) warp_sums[w] = v;
    __syncthreads();
    if (w == 0) {
        int s = warp_sums[lane];
        #pragma unroll
        for (int o = 1; o < 32; o <<= 1) {
            int t = __shfl_up_sync(0xFFFFFFFFu, s, o);
            if (lane >= o) s += t;
        }
        warp_sums[lane] = s;
    }
    __syncthreads();
    int excl = v - x + ((w == 0) ? 0 : warp_sums[w - 1]);
    if (i < N_NODES) {
        int val = g_partoff[blockIdx.x] + excl;
        g_row_ptr[i] = val;
        g_cursor[i]  = val;
    }
}
__global__ void k_scatter(const void* src, const void* dst,
                          const float* __restrict__ ew) {
    int e = blockIdx.x * blockDim.x + threadIdx.x;
    if (e < N_EDGES) {
        int is64 = g_idx64;
        int d = load_idx(dst, e, is64);
        int pos = atomicAdd(&g_cursor[d], 1);
        Edge ed; ed.s = load_idx(src, e, is64); ed.w = ew[e];
        g_edges[pos] = ed;
    }
}

// ---------------- weight prep: transpose + split into bf16 hi/lo ----------
template <int K, int N>
__global__ void k_prepB(const float* __restrict__ W,
                        __nv_bfloat16* __restrict__ outh,
                        __nv_bfloat16* __restrict__ outl) {
    int t = blockIdx.x * blockDim.x + threadIdx.x;
    if (t < K * N) {
        int n = t / K, k = t % K;
        float v = W[(size_t)k * N + n];
        __nv_bfloat16 h = __float2bfloat16_rn(v);
        outh[t] = h;
        outl[t] = __float2bfloat16_rn(v - __bfloat162float(h));
    }
}

// ---------------- split-bf16 tensor-core GEMM, 1-sync pipeline + ldmatrix --
__device__ __forceinline__ void mma16816(float* c, const unsigned* a,
                                         const unsigned* b) {
    asm volatile(
        "mma.sync.aligned.m16n8k16.row.col.f32.bf16.bf16.f32 "
        "{%0,%1,%2,%3}, {%4,%5,%6,%7}, {%8,%9}, {%0,%1,%2,%3};\n"
        : "+f"(c[0]), "+f"(c[1]), "+f"(c[2]), "+f"(c[3])
        : "r"(a[0]), "r"(a[1]), "r"(a[2]), "r"(a[3]), "r"(b[0]), "r"(b[1]));
}
#define LDSM_X4(r, a)                                                        \
    asm volatile("ldmatrix.sync.aligned.m8n8.x4.shared.b16 "                 \
                 "{%0,%1,%2,%3}, [%4];"                                      \
                 : "=r"((r)[0]), "=r"((r)[1]), "=r"((r)[2]), "=r"((r)[3])    \
                 : "r"(a))

// C[M,BN] = A[M,K](fp32, split in-kernel) @ Bt(pre-split [n][k] bf16)
// BM=128, BK=32. 8 warps. ONE __syncthreads per k-tile:
//  iter kt: wait cp(kt); sync (st^1 now reader-free); cpB(kt+1)->st^1 async
//  under compute(st); stsA(st^1) post-compute; fast warps fenced by next
//  iter's wait+sync.
template <int K, int BN>
__global__ __launch_bounds__(256, 2) void k_mma_gemm(
    const float* __restrict__ A,
    const __nv_bfloat16* __restrict__ Bh,
    const __nv_bfloat16* __restrict__ Bl,
    float* __restrict__ C, int M) {
    constexpr int NWN = BN / 32;
    constexpr int NWM = 8 / NWN;
    constexpr int WTM = 128 / NWM;
    constexpr int MT  = WTM / 16;
    constexpr int KT  = K / 32;
    constexpr int A_ST = 128 * 20;   // words per stage (per hi/lo matrix)
    constexpr int B_ST = BN * 20;

    extern __shared__ char smem_raw[];
    unsigned* Ash = (unsigned*)smem_raw;                 // [2][A_ST]
    unsigned* Asl = Ash + 2 * A_ST;
    unsigned* Bsh = Asl + 2 * A_ST;                      // [2][B_ST]
    unsigned* Bsl = Bsh + 2 * B_ST;

    const int tid = threadIdx.x;
    const int wid = tid >> 5, lane = tid & 31;
    const int wm = wid / NWN, wn = wid % NWN;
    const int gid = lane >> 2, t4 = lane & 3;
    const int bm0 = blockIdx.x * 128;

    unsigned sBh = (unsigned)__cvta_generic_to_shared(Bsh);
    unsigned sBl = (unsigned)__cvta_generic_to_shared(Bsl);

    // ---- per-lane ldmatrix base addresses (bytes) ----
    const int rowA = wm * WTM + (lane & 7) + ((lane >> 3) & 1) * 8;
    const int colA = ((lane >> 4) & 1) * 4;
    const unsigned aOff = (unsigned)(rowA * 20 + colA) * 4u;
    const unsigned aAddrH = (unsigned)__cvta_generic_to_shared(Ash) + aOff;
    const unsigned aAddrL = (unsigned)__cvta_generic_to_shared(Asl) + aOff;
    const int rowB = wn * 32 + (lane & 7) + ((lane >> 4) & 1) * 8;
    const int colB = ((lane >> 3) & 1) * 4;
    const unsigned bOff = (unsigned)(rowB * 20 + colB) * 4u;
    const unsigned bAddrH = sBh + bOff;
    const unsigned bAddrL = sBl + bOff;

    // ---- A register staging: 4 float4 per thread per stage ----
    float4 areg[4];
    auto ldgA = [&](int kt) {
        int k0 = kt * 32;
        #pragma unroll
        for (int i = 0; i < 4; i++) {
            int linear = tid + 256 * i;
            int row = linear >> 3, c4 = linear & 7;
            int gr = bm0 + row;
            areg[i] = (gr < M)
                ? *(const float4*)(A + (size_t)gr * K + k0 + c4 * 4)
                : make_float4(0.f, 0.f, 0.f, 0.f);
        }
    };
    auto stsA = [&](int st) {
        #pragma unroll
        for (int i = 0; i < 4; i++) {
            int linear = tid + 256 * i;
            int row = linear >> 3, c4 = linear & 7;
            float f[4] = {areg[i].x, areg[i].y, areg[i].z, areg[i].w};
            unsigned short hh[4], ll[4];
            #pragma unroll
            for (int c = 0; c < 4; c++) {
                __nv_bfloat16 h = __float2bfloat16_rn(f[c]);
                __nv_bfloat16 l = __float2bfloat16_rn(f[c] - __bfloat162float(h));
                hh[c] = __bfloat16_as_ushort(h);
                ll[c] = __bfloat16_as_ushort(l);
            }
            uint2 ph = make_uint2((unsigned)hh[0] | ((unsigned)hh[1] << 16),
                                  (unsigned)hh[2] | ((unsigned)hh[3] << 16));
            uint2 pl = make_uint2((unsigned)ll[0] | ((unsigned)ll[1] << 16),
                                  (unsigned)ll[2] | ((unsigned)ll[3] << 16));
            *(uint2*)&Ash[st * A_ST + row * 20 + c4 * 2] = ph;
            *(uint2*)&Asl[st * A_ST + row * 20 + c4 * 2] = pl;
        }
    };
    auto cpB = [&](int kt, int st) {
        int k0 = kt * 32;
        constexpr int BI = (BN * 4) / 256;
        #pragma unroll
        for (int i = 0; i < BI; i++) {
            int linear = tid + 256 * i;
            int row = linear >> 2, j = linear & 3;
            unsigned dh = sBh + (st * B_ST + row * 20 + j * 4) * 4;
            unsigned dl = sBl + (st * B_ST + row * 20 + j * 4) * 4;
            const __nv_bfloat16* ph = Bh + (size_t)row * K + k0 + j * 8;
            const __nv_bfloat16* pl = Bl + (size_t)row * K + k0 + j * 8;
            asm volatile("cp.async.ca.shared.global [%0], [%1], 16;\n" :: "r"(dh), "l"(ph));
            asm volatile("cp.async.ca.shared.global [%0], [%1], 16;\n" :: "r"(dl), "l"(pl));
        }
        asm volatile("cp.async.commit_group;\n");
    };

    float acc[MT][4][4];
    #pragma unroll
    for (int m = 0; m < MT; m++)
        #pragma unroll
        for (int n = 0; n < 4; n++)
            #pragma unroll
            for (int r = 0; r < 4; r++) acc[m][n][r] = 0.f;

    // prologue: fill stage 0; preload A regs for stage 1
    ldgA(0);
    cpB(0, 0);
    stsA(0);
    if (KT > 1) ldgA(1);

    for (int kt = 0; kt < KT; kt++) {
        const int st = kt & 1;
        asm volatile("cp.async.wait_group 0;\n");  // stage kt B arrived
        __syncthreads();   // stage kt visible; buf st^1 has no readers left

        if (kt + 1 < KT) cpB(kt + 1, st ^ 1);      // async fill under compute

        const unsigned aStOff = (unsigned)(st * A_ST) * 4u;
        const unsigned bStOff = (unsigned)(st * B_ST) * 4u;
        #pragma unroll
        for (int kk = 0; kk < 2; kk++) {
            const unsigned kOff = (unsigned)(kk * 8) * 4u;
            unsigned bh[2][4], bl[2][4];
            #pragma unroll
            for (int p = 0; p < 2; p++) {
                unsigned po = (unsigned)(p * 16 * 20) * 4u;
                LDSM_X4(bh[p], bAddrH + bStOff + kOff + po);
                LDSM_X4(bl[p], bAddrL + bStOff + kOff + po);
            }
            #pragma unroll
            for (int mt = 0; mt < MT; mt++) {
                unsigned mo = (unsigned)(mt * 16 * 20) * 4u;
                unsigned ah[4], al[4];
                LDSM_X4(ah, aAddrH + aStOff + kOff + mo);
                LDSM_X4(al, aAddrL + aStOff + kOff + mo);
                #pragma unroll
                for (int nt = 0; nt < 4; nt++) {
                    const unsigned* bhp = &bh[nt >> 1][(nt & 1) * 2];
                    const unsigned* blp = &bl[nt >> 1][(nt & 1) * 2];
                    mma16816(acc[mt][nt], ah, bhp);
                    mma16816(acc[mt][nt], ah, blp);
                    mma16816(acc[mt][nt], al, bhp);
                }
            }
        }
        if (kt + 1 < KT) {
            stsA(st ^ 1);                 // A for kt+1 (areg loaded earlier)
            if (kt + 2 < KT) ldgA(kt + 2);
        }
    }

    // ---- epilogue ----
    #pragma unroll
    for (int mt = 0; mt < MT; mt++) {
        int r = bm0 + wm * WTM + mt * 16 + gid;
        #pragma unroll
        for (int nt = 0; nt < 4; nt++) {
            int c = wn * 32 + nt * 8 + 2 * t4;
            if (r < M)
                *(float2*)&C[(size_t)r * BN + c] =
                    make_float2(acc[mt][nt][0], acc[mt][nt][1]);
            if (r + 8 < M)
                *(float2*)&C[(size_t)(r + 8) * BN + c] =
                    make_float2(acc[mt][nt][2], acc[mt][nt][3]);
        }
    }
}

// ---------------- layer-1 aggregation: warp per node, fused bias+leaky ----
__global__ void k_agg1(const float* __restrict__ sup,
                       const float* __restrict__ bias,
                       float* __restrict__ h) {
    int gw = (blockIdx.x * blockDim.x + threadIdx.x) >> 5;
    if (gw >= N_NODES) return;
    int lane = threadIdx.x & 31;
    int beg = g_row_ptr[gw], end = g_row_ptr[gw + 1];
    float4 a0 = make_float4(0.f, 0.f, 0.f, 0.f);
    float4 a1 = make_float4(0.f, 0.f, 0.f, 0.f);
    int e = beg;
    for (; e + 2 <= end; e += 2) {
        Edge e0 = g_edges[e], e1 = g_edges[e + 1];
        float4 v0 = ((const float4*)(sup + (size_t)e0.s * NHID))[lane];
        float4 v1 = ((const float4*)(sup + (size_t)e1.s * NHID))[lane];
        a0.x += e0.w * v0.x; a0.y += e0.w * v0.y; a0.z += e0.w * v0.z; a0.w += e0.w * v0.w;
        a1.x += e1.w * v1.x; a1.y += e1.w * v1.y; a1.z += e1.w * v1.z; a1.w += e1.w * v1.w;
    }
    if (e < end) {
        Edge e0 = g_edges[e];
        float4 v0 = ((const float4*)(sup + (size_t)e0.s * NHID))[lane];
        a0.x += e0.w * v0.x; a0.y += e0.w * v0.y; a0.z += e0.w * v0.z; a0.w += e0.w * v0.w;
    }
    float4 bb = ((const float4*)bias)[lane];
    float4 r;
    r.x = a0.x + a1.x + bb.x;
    r.y = a0.y + a1.y + bb.y;
    r.z = a0.z + a1.z + bb.z;
    r.w = a0.w + a1.w + bb.w;
    r.x = r.x > 0.f ? r.x : 0.01f * r.x;
    r.y = r.y > 0.f ? r.y : 0.01f * r.y;
    r.z = r.z > 0.f ? r.z : 0.01f * r.z;
    r.w = r.w > 0.f ? r.w : 0.01f * r.w;
    ((float4*)(h + (size_t)gw * NHID))[lane] = r;
}

// ------- layer-2 aggregation: warp per node, fused bias + softmax --------
__global__ void k_agg2(const float* __restrict__ sup,
                       const float* __restrict__ bias,
                       float* __restrict__ out) {
    int gw = (blockIdx.x * blockDim.x + threadIdx.x) >> 5;
    if (gw >= N_NODES) return;
    int lane = threadIdx.x & 31;
    int beg = g_row_ptr[gw], end = g_row_ptr[gw + 1];
    float2 a0 = make_float2(0.f, 0.f);
    float2 a1 = make_float2(0.f, 0.f);
    int e = beg;
    for (; e + 2 <= end; e += 2) {
        Edge e0 = g_edges[e], e1 = g_edges[e + 1];
        float2 v0 = ((const float2*)(sup + (size_t)e0.s * NCLASS))[lane];
        float2 v1 = ((const float2*)(sup + (size_t)e1.s * NCLASS))[lane];
        a0.x += e0.w * v0.x; a0.y += e0.w * v0.y;
        a1.x += e1.w * v1.x; a1.y += e1.w * v1.y;
    }
    if (e < end) {
        Edge e0 = g_edges[e];
        float2 v0 = ((const float2*)(sup + (size_t)e0.s * NCLASS))[lane];
        a0.x += e0.w * v0.x; a0.y += e0.w * v0.y;
    }
    float2 bb = ((const float2*)bias)[lane];
    float lx = a0.x + a1.x + bb.x;
    float ly = a0.y + a1.y + bb.y;
    float m = fmaxf(lx, ly);
    #pragma unroll
    for (int o = 16; o > 0; o >>= 1)
        m = fmaxf(m, __shfl_xor_sync(0xFFFFFFFFu, m, o));
    float ex = __expf(lx - m), ey = __expf(ly - m);
    float s = ex + ey;
    #pragma unroll
    for (int o = 16; o > 0; o >>= 1)
        s += __shfl_xor_sync(0xFFFFFFFFu, s, o);
    float inv = 1.f / s;
    ((float2*)(out + (size_t)gw * NCLASS))[lane] = make_float2(ex * inv, ey * inv);
}

// ---------------- launch ----------------
extern "C" void kernel_launch(void* const* d_in, const int* in_sizes, int n_in,
                              void* d_out, int out_size) {
    const float* y    = (const float*)d_in[0];
    const void*  srcp = d_in[1];
    const void*  dstp = d_in[2];
    const float* ew   = (const float*)d_in[3];
    const float* W1   = (const float*)d_in[4];
    const float* b1   = (const float*)d_in[5];
    const float* W2   = (const float*)d_in[6];
    const float* b2   = (const float*)d_in[7];

    float* out_softmax = (float*)d_out;                              // [N, 64]
    float* out_emb     = (float*)d_out + (size_t)N_NODES * NCLASS;   // [N, 128]

    float* sup1; cudaGetSymbolAddress((void**)&sup1, g_support1);
    float* sup2; cudaGetSymbolAddress((void**)&sup2, g_support2);
    __nv_bfloat16 *b1h, *b1l, *b2h, *b2l;
    cudaGetSymbolAddress((void**)&b1h, g_B1t_h);
    cudaGetSymbolAddress((void**)&b1l, g_B1t_l);
    cudaGetSymbolAddress((void**)&b2h, g_B2t_h);
    cudaGetSymbolAddress((void**)&b2l, g_B2t_l);

    // smem: A hi/lo 2 stages (40960B) + B hi/lo 2 stages
    const int SMEM1 = 40960 + 40960;   // BN=128
    const int SMEM2 = 40960 + 20480;   // BN=64
    static bool init_done = false;
    static cudaStream_t s2 = nullptr;
    static cudaEvent_t evFork = nullptr, evJoin = nullptr;
    if (!init_done) {
        cudaFuncSetAttribute(k_mma_gemm<NFEAT, NHID>,
                             cudaFuncAttributeMaxDynamicSharedMemorySize, SMEM1);
        cudaFuncSetAttribute(k_mma_gemm<NHID, NCLASS>,
                             cudaFuncAttributeMaxDynamicSharedMemorySize, SMEM2);
        cudaStreamCreateWithFlags(&s2, cudaStreamNonBlocking);
        cudaEventCreateWithFlags(&evFork, cudaEventDisableTiming);
        cudaEventCreateWithFlags(&evJoin, cudaEventDisableTiming);
        init_done = true;
    }

    // ---- fork: CSR build + W2 prep on side stream, hidden under GEMM1 ----
    cudaEventRecord(evFork, 0);
    cudaStreamWaitEvent(s2, evFork, 0);

    k_prepB<NHID, NCLASS><<<(NHID * NCLASS + 255) / 256, 256, 0, s2>>>(W2, b2h, b2l);
    k_detect<<<1, 1, 0, s2>>>(dstp);
    k_zero_cnt<<<(N_NODES + 255) / 256, 256, 0, s2>>>();
    k_count<<<(N_EDGES + 255) / 256, 256, 0, s2>>>(dstp);
    k_partsum<<<SCAN_BLOCKS, 1024, 0, s2>>>();
    k_scanpart<<<1, 128, 0, s2>>>();
    k_scanfinal<<<SCAN_BLOCKS, 1024, 0, s2>>>();
    k_scatter<<<(N_EDGES + 255) / 256, 256, 0, s2>>>(srcp, dstp, ew);
    cudaEventRecord(evJoin, s2);

    // ---- main stream: dense chain ----
    k_prepB<NFEAT, NHID><<<(NFEAT * NHID + 255) / 256, 256>>>(W1, b1h, b1l);

    const int gblocks = (N_NODES + 127) / 128;
    k_mma_gemm<NFEAT, NHID><<<gblocks, 256, SMEM1>>>(y, b1h, b1l, sup1, N_NODES);

    // ---- join: agg needs CSR ----
    cudaStreamWaitEvent(0, evJoin, 0);

    k_agg1<<<(N_NODES * 32 + 255) / 256, 256>>>(sup1, b1, out_emb);
    k_mma_gemm<NHID, NCLASS><<<gblocks, 256, SMEM2>>>(out_emb, b2h, b2l, sup2,
                                                      N_NODES);
    k_agg2<<<(N_NODES * 32 + 255) / 256, 256>>>(sup2, b2, out_softmax);
}

// round 8
// speedup vs baseline: 1.2062x; 1.1075x over previous
#include <cuda_runtime.h>
#include <cuda_bf16.h>
#include <cuda_fp16.h>
#include <cstdint>

#define N_NODES 100000
#define N_EDGES 1600000
#define NFEAT   512
#define NHID    128
#define NCLASS  64
#define SCAN_BLOCKS ((N_NODES + 1023) / 1024)   // 98

// ---------------- device scratch (no allocations allowed) ----------------
struct __align__(8) Edge { int s; float w; };

__device__ float g_support1[(size_t)N_NODES * NHID];
__device__ float g_support2[(size_t)N_NODES * NCLASS];
__device__ int   g_cnt[N_NODES];
__device__ int   g_row_ptr[N_NODES + 1];
__device__ int   g_cursor[N_NODES + 1];
__device__ Edge  g_edges[N_EDGES];
__device__ int   g_idx64;
__device__ int   g_part[SCAN_BLOCKS];
__device__ int   g_partoff[SCAN_BLOCKS];
// W1 transposed, single fp16 (2-product path uses split-A only)
__device__ __align__(16) __half        g_B1t_h[NHID * NFEAT];
// W2 transposed, split bf16 hi/lo (3-product path)
__device__ __align__(16) __nv_bfloat16 g_B2t_h[NCLASS * NHID];
__device__ __align__(16) __nv_bfloat16 g_B2t_l[NCLASS * NHID];

// ---------------- index dtype detection ----------------
__global__ void k_detect(const void* dst) {
    if (threadIdx.x == 0 && blockIdx.x == 0) {
        const unsigned long long* p = (const unsigned long long*)dst;
        int is64 = 1;
        #pragma unroll
        for (int i = 0; i < 8; i++)
            if (p[i] >= (unsigned long long)N_NODES) is64 = 0;
        g_idx64 = is64;
    }
}
__device__ __forceinline__ int load_idx(const void* p, int i, int is64) {
    return is64 ? (int)((const long long*)p)[i] : ((const int*)p)[i];
}

// ---------------- CSR build ----------------
__global__ void k_zero_cnt() {
    int i = blockIdx.x * blockDim.x + threadIdx.x;
    if (i < N_NODES) g_cnt[i] = 0;
}
__global__ void k_count(const void* dst) {
    int e = blockIdx.x * blockDim.x + threadIdx.x;
    if (e < N_EDGES) {
        int is64 = g_idx64;
        atomicAdd(&g_cnt[load_idx(dst, e, is64)], 1);
    }
}
__global__ void k_partsum() {
    int i = blockIdx.x * 1024 + threadIdx.x;
    int x = (i < N_NODES) ? g_cnt[i] : 0;
    #pragma unroll
    for (int o = 16; o > 0; o >>= 1) x += __shfl_xor_sync(0xFFFFFFFFu, x, o);
    __shared__ int ws[32];
    int lane = threadIdx.x & 31, w = threadIdx.x >> 5;
    if (lane == 0) ws[w] = x;
    __syncthreads();
    if (w == 0) {
        int v = ws[lane];
        #pragma unroll
        for (int o = 16; o > 0; o >>= 1) v += __shfl_xor_sync(0xFFFFFFFFu, v, o);
        if (lane == 0) g_part[blockIdx.x] = v;
    }
}
__global__ void k_scanpart() {
    __shared__ int s[128];
    int tid = threadIdx.x;
    int x = (tid < SCAN_BLOCKS) ? g_part[tid] : 0;
    s[tid] = x;
    __syncthreads();
    #pragma unroll
    for (int off = 1; off < 128; off <<= 1) {
        int t = (tid >= off) ? s[tid - off] : 0;
        __syncthreads();
        s[tid] += t;
        __syncthreads();
    }
    if (tid < SCAN_BLOCKS) g_partoff[tid] = s[tid] - x;
    if (tid == 127) g_row_ptr[N_NODES] = s[127];
}
__global__ void k_scanfinal() {
    __shared__ int warp_sums[32];
    int tid = threadIdx.x;
    int lane = tid & 31, w = tid >> 5;
    int i = blockIdx.x * 1024 + tid;
    int x = (i < N_NODES) ? g_cnt[i] : 0;
    int v = x;
    #pragma unroll
    for (int o = 1; o < 32; o <<= 1) {
        int t = __shfl_up_sync(0xFFFFFFFFu, v, o);
        if (lane >= o) v += t;
    }
    if (lane == 31) warp_sums[w] = v;
    __syncthreads();
    if (w == 0) {
        int s = warp_sums[lane];
        #pragma unroll
        for (int o = 1; o < 32; o <<= 1) {
            int t = __shfl_up_sync(0xFFFFFFFFu, s, o);
            if (lane >= o) s += t;
        }
        warp_sums[lane] = s;
    }
    __syncthreads();
    int excl = v - x + ((w == 0) ? 0 : warp_sums[w - 1]);
    if (i < N_NODES) {
        int val = g_partoff[blockIdx.x] + excl;
        g_row_ptr[i] = val;
        g_cursor[i]  = val;
    }
}
__global__ void k_scatter(const void* src, const void* dst,
                          const float* __restrict__ ew) {
    int e = blockIdx.x * blockDim.x + threadIdx.x;
    if (e < N_EDGES) {
        int is64 = g_idx64;
        int d = load_idx(dst, e, is64);
        int pos = atomicAdd(&g_cursor[d], 1);
        Edge ed; ed.s = load_idx(src, e, is64); ed.w = ew[e];
        g_edges[pos] = ed;
    }
}

// ---------------- weight prep ----------------
// W1: transpose + single fp16
template <int K, int N>
__global__ void k_prepBh(const float* __restrict__ W,
                         __half* __restrict__ outh) {
    int t = blockIdx.x * blockDim.x + threadIdx.x;
    if (t < K * N) {
        int n = t / K, k = t % K;
        outh[t] = __float2half_rn(W[(size_t)k * N + n]);
    }
}
// W2: transpose + split bf16 hi/lo
template <int K, int N>
__global__ void k_prepB(const float* __restrict__ W,
                        __nv_bfloat16* __restrict__ outh,
                        __nv_bfloat16* __restrict__ outl) {
    int t = blockIdx.x * blockDim.x + threadIdx.x;
    if (t < K * N) {
        int n = t / K, k = t % K;
        float v = W[(size_t)k * N + n];
        __nv_bfloat16 h = __float2bfloat16_rn(v);
        outh[t] = h;
        outl[t] = __float2bfloat16_rn(v - __bfloat162float(h));
    }
}

// ---------------- mixed-precision tensor-core GEMM, 1-sync pipeline -------
__device__ __forceinline__ void mma_bf16(float* c, const unsigned* a,
                                         const unsigned* b) {
    asm volatile(
        "mma.sync.aligned.m16n8k16.row.col.f32.bf16.bf16.f32 "
        "{%0,%1,%2,%3}, {%4,%5,%6,%7}, {%8,%9}, {%0,%1,%2,%3};\n"
        : "+f"(c[0]), "+f"(c[1]), "+f"(c[2]), "+f"(c[3])
        : "r"(a[0]), "r"(a[1]), "r"(a[2]), "r"(a[3]), "r"(b[0]), "r"(b[1]));
}
__device__ __forceinline__ void mma_f16(float* c, const unsigned* a,
                                        const unsigned* b) {
    asm volatile(
        "mma.sync.aligned.m16n8k16.row.col.f32.f16.f16.f32 "
        "{%0,%1,%2,%3}, {%4,%5,%6,%7}, {%8,%9}, {%0,%1,%2,%3};\n"
        : "+f"(c[0]), "+f"(c[1]), "+f"(c[2]), "+f"(c[3])
        : "r"(a[0]), "r"(a[1]), "r"(a[2]), "r"(a[3]), "r"(b[0]), "r"(b[1]));
}
#define LDSM_X4(r, a)                                                        \
    asm volatile("ldmatrix.sync.aligned.m8n8.x4.shared.b16 "                 \
                 "{%0,%1,%2,%3}, [%4];"                                      \
                 : "=r"((r)[0]), "=r"((r)[1]), "=r"((r)[2]), "=r"((r)[3])    \
                 : "r"(a))

// F16_2P=true : A split fp16 hi/lo, B single fp16 -> 2 MMA products
// F16_2P=false: A split bf16 hi/lo, B split bf16  -> 3 MMA products
// BM=128, BK=32, 8 warps, one __syncthreads per k-tile (validated R7).
template <int K, int BN, bool F16_2P>
__global__ __launch_bounds__(256, 2) void k_mma_gemm(
    const float* __restrict__ A,
    const void* __restrict__ Bhv,
    const void* __restrict__ Blv,
    float* __restrict__ C, int M) {
    constexpr int NWN = BN / 32;
    constexpr int NWM = 8 / NWN;
    constexpr int WTM = 128 / NWM;
    constexpr int MT  = WTM / 16;
    constexpr int KT  = K / 32;
    constexpr int A_ST = 128 * 20;   // words per stage per matrix
    constexpr int B_ST = BN * 20;

    const __nv_bfloat16* Bh = (const __nv_bfloat16*)Bhv;
    const __nv_bfloat16* Bl = (const __nv_bfloat16*)Blv;

    extern __shared__ char smem_raw[];
    unsigned* Ash = (unsigned*)smem_raw;                 // [2][A_ST]
    unsigned* Asl = Ash + 2 * A_ST;
    unsigned* Bsh = Asl + 2 * A_ST;                      // [2][B_ST]
    unsigned* Bsl = Bsh + 2 * B_ST;                      // only if !F16_2P

    const int tid = threadIdx.x;
    const int wid = tid >> 5, lane = tid & 31;
    const int wm = wid / NWN, wn = wid % NWN;
    const int gid = lane >> 2, t4 = lane & 3;
    const int bm0 = blockIdx.x * 128;

    unsigned sBh = (unsigned)__cvta_generic_to_shared(Bsh);
    unsigned sBl = (unsigned)__cvta_generic_to_shared(Bsl);

    // ---- per-lane ldmatrix base addresses (bytes) ----
    const int rowA = wm * WTM + (lane & 7) + ((lane >> 3) & 1) * 8;
    const int colA = ((lane >> 4) & 1) * 4;
    const unsigned aOff = (unsigned)(rowA * 20 + colA) * 4u;
    const unsigned aAddrH = (unsigned)__cvta_generic_to_shared(Ash) + aOff;
    const unsigned aAddrL = (unsigned)__cvta_generic_to_shared(Asl) + aOff;
    const int rowB = wn * 32 + (lane & 7) + ((lane >> 4) & 1) * 8;
    const int colB = ((lane >> 3) & 1) * 4;
    const unsigned bOff = (unsigned)(rowB * 20 + colB) * 4u;
    const unsigned bAddrH = sBh + bOff;
    const unsigned bAddrL = sBl + bOff;

    // ---- A register staging: 4 float4 per thread per stage ----
    float4 areg[4];
    auto ldgA = [&](int kt) {
        int k0 = kt * 32;
        #pragma unroll
        for (int i = 0; i < 4; i++) {
            int linear = tid + 256 * i;
            int row = linear >> 3, c4 = linear & 7;
            int gr = bm0 + row;
            areg[i] = (gr < M)
                ? *(const float4*)(A + (size_t)gr * K + k0 + c4 * 4)
                : make_float4(0.f, 0.f, 0.f, 0.f);
        }
    };
    auto stsA = [&](int st) {
        #pragma unroll
        for (int i = 0; i < 4; i++) {
            int linear = tid + 256 * i;
            int row = linear >> 3, c4 = linear & 7;
            float f[4] = {areg[i].x, areg[i].y, areg[i].z, areg[i].w};
            unsigned short hh[4], ll[4];
            #pragma unroll
            for (int c = 0; c < 4; c++) {
                if (F16_2P) {
                    __half h = __float2half_rn(f[c]);
                    __half l = __float2half_rn(f[c] - __half2float(h));
                    hh[c] = __half_as_ushort(h);
                    ll[c] = __half_as_ushort(l);
                } else {
                    __nv_bfloat16 h = __float2bfloat16_rn(f[c]);
                    __nv_bfloat16 l =
                        __float2bfloat16_rn(f[c] - __bfloat162float(h));
                    hh[c] = __bfloat16_as_ushort(h);
                    ll[c] = __bfloat16_as_ushort(l);
                }
            }
            uint2 ph = make_uint2((unsigned)hh[0] | ((unsigned)hh[1] << 16),
                                  (unsigned)hh[2] | ((unsigned)hh[3] << 16));
            uint2 pl = make_uint2((unsigned)ll[0] | ((unsigned)ll[1] << 16),
                                  (unsigned)ll[2] | ((unsigned)ll[3] << 16));
            *(uint2*)&Ash[st * A_ST + row * 20 + c4 * 2] = ph;
            *(uint2*)&Asl[st * A_ST + row * 20 + c4 * 2] = pl;
        }
    };
    auto cpB = [&](int kt, int st) {
        int k0 = kt * 32;
        constexpr int BI = (BN * 4) / 256;
        #pragma unroll
        for (int i = 0; i < BI; i++) {
            int linear = tid + 256 * i;
            int row = linear >> 2, j = linear & 3;
            unsigned dh = sBh + (st * B_ST + row * 20 + j * 4) * 4;
            const __nv_bfloat16* ph = Bh + (size_t)row * K + k0 + j * 8;
            asm volatile("cp.async.ca.shared.global [%0], [%1], 16;\n" :: "r"(dh), "l"(ph));
            if (!F16_2P) {
                unsigned dl = sBl + (st * B_ST + row * 20 + j * 4) * 4;
                const __nv_bfloat16* pl = Bl + (size_t)row * K + k0 + j * 8;
                asm volatile("cp.async.ca.shared.global [%0], [%1], 16;\n" :: "r"(dl), "l"(pl));
            }
        }
        asm volatile("cp.async.commit_group;\n");
    };

    float acc[MT][4][4];
    #pragma unroll
    for (int m = 0; m < MT; m++)
        #pragma unroll
        for (int n = 0; n < 4; n++)
            #pragma unroll
            for (int r = 0; r < 4; r++) acc[m][n][r] = 0.f;

    // prologue: fill stage 0; preload A regs for stage 1
    ldgA(0);
    cpB(0, 0);
    stsA(0);
    if (KT > 1) ldgA(1);

    for (int kt = 0; kt < KT; kt++) {
        const int st = kt & 1;
        asm volatile("cp.async.wait_group 0;\n");
        __syncthreads();   // stage kt visible; buf st^1 reader-free

        if (kt + 1 < KT) cpB(kt + 1, st ^ 1);

        const unsigned aStOff = (unsigned)(st * A_ST) * 4u;
        const unsigned bStOff = (unsigned)(st * B_ST) * 4u;
        #pragma unroll
        for (int kk = 0; kk < 2; kk++) {
            const unsigned kOff = (unsigned)(kk * 8) * 4u;
            unsigned bh[2][4], bl[2][4];
            #pragma unroll
            for (int p = 0; p < 2; p++) {
                unsigned po = (unsigned)(p * 16 * 20) * 4u;
                LDSM_X4(bh[p], bAddrH + bStOff + kOff + po);
                if (!F16_2P) LDSM_X4(bl[p], bAddrL + bStOff + kOff + po);
            }
            #pragma unroll
            for (int mt = 0; mt < MT; mt++) {
                unsigned mo = (unsigned)(mt * 16 * 20) * 4u;
                unsigned ah[4], al[4];
                LDSM_X4(ah, aAddrH + aStOff + kOff + mo);
                LDSM_X4(al, aAddrL + aStOff + kOff + mo);
                #pragma unroll
                for (int nt = 0; nt < 4; nt++) {
                    const unsigned* bhp = &bh[nt >> 1][(nt & 1) * 2];
                    if (F16_2P) {
                        mma_f16(acc[mt][nt], ah, bhp);
                        mma_f16(acc[mt][nt], al, bhp);
                    } else {
                        const unsigned* blp = &bl[nt >> 1][(nt & 1) * 2];
                        mma_bf16(acc[mt][nt], ah, bhp);
                        mma_bf16(acc[mt][nt], ah, blp);
                        mma_bf16(acc[mt][nt], al, bhp);
                    }
                }
            }
        }
        if (kt + 1 < KT) {
            stsA(st ^ 1);
            if (kt + 2 < KT) ldgA(kt + 2);
        }
    }

    // ---- epilogue ----
    #pragma unroll
    for (int mt = 0; mt < MT; mt++) {
        int r = bm0 + wm * WTM + mt * 16 + gid;
        #pragma unroll
        for (int nt = 0; nt < 4; nt++) {
            int c = wn * 32 + nt * 8 + 2 * t4;
            if (r < M)
                *(float2*)&C[(size_t)r * BN + c] =
                    make_float2(acc[mt][nt][0], acc[mt][nt][1]);
            if (r + 8 < M)
                *(float2*)&C[(size_t)(r + 8) * BN + c] =
                    make_float2(acc[mt][nt][2], acc[mt][nt][3]);
        }
    }
}

// ---------------- layer-1 aggregation: warp per node, fused bias+leaky ----
__global__ void k_agg1(const float* __restrict__ sup,
                       const float* __restrict__ bias,
                       float* __restrict__ h) {
    int gw = (blockIdx.x * blockDim.x + threadIdx.x) >> 5;
    if (gw >= N_NODES) return;
    int lane = threadIdx.x & 31;
    int beg = g_row_ptr[gw], end = g_row_ptr[gw + 1];
    float4 a0 = make_float4(0.f, 0.f, 0.f, 0.f);
    float4 a1 = make_float4(0.f, 0.f, 0.f, 0.f);
    int e = beg;
    for (; e + 2 <= end; e += 2) {
        Edge e0 = g_edges[e], e1 = g_edges[e + 1];
        float4 v0 = ((const float4*)(sup + (size_t)e0.s * NHID))[lane];
        float4 v1 = ((const float4*)(sup + (size_t)e1.s * NHID))[lane];
        a0.x += e0.w * v0.x; a0.y += e0.w * v0.y; a0.z += e0.w * v0.z; a0.w += e0.w * v0.w;
        a1.x += e1.w * v1.x; a1.y += e1.w * v1.y; a1.z += e1.w * v1.z; a1.w += e1.w * v1.w;
    }
    if (e < end) {
        Edge e0 = g_edges[e];
        float4 v0 = ((const float4*)(sup + (size_t)e0.s * NHID))[lane];
        a0.x += e0.w * v0.x; a0.y += e0.w * v0.y; a0.z += e0.w * v0.z; a0.w += e0.w * v0.w;
    }
    float4 bb = ((const float4*)bias)[lane];
    float4 r;
    r.x = a0.x + a1.x + bb.x;
    r.y = a0.y + a1.y + bb.y;
    r.z = a0.z + a1.z + bb.z;
    r.w = a0.w + a1.w + bb.w;
    r.x = r.x > 0.f ? r.x : 0.01f * r.x;
    r.y = r.y > 0.f ? r.y : 0.01f * r.y;
    r.z = r.z > 0.f ? r.z : 0.01f * r.z;
    r.w = r.w > 0.f ? r.w : 0.01f * r.w;
    ((float4*)(h + (size_t)gw * NHID))[lane] = r;
}

// ------- layer-2 aggregation: warp per node, fused bias + softmax --------
__global__ void k_agg2(const float* __restrict__ sup,
                       const float* __restrict__ bias,
                       float* __restrict__ out) {
    int gw = (blockIdx.x * blockDim.x + threadIdx.x) >> 5;
    if (gw >= N_NODES) return;
    int lane = threadIdx.x & 31;
    int beg = g_row_ptr[gw], end = g_row_ptr[gw + 1];
    float2 a0 = make_float2(0.f, 0.f);
    float2 a1 = make_float2(0.f, 0.f);
    int e = beg;
    for (; e + 2 <= end; e += 2) {
        Edge e0 = g_edges[e], e1 = g_edges[e + 1];
        float2 v0 = ((const float2*)(sup + (size_t)e0.s * NCLASS))[lane];
        float2 v1 = ((const float2*)(sup + (size_t)e1.s * NCLASS))[lane];
        a0.x += e0.w * v0.x; a0.y += e0.w * v0.y;
        a1.x += e1.w * v1.x; a1.y += e1.w * v1.y;
    }
    if (e < end) {
        Edge e0 = g_edges[e];
        float2 v0 = ((const float2*)(sup + (size_t)e0.s * NCLASS))[lane];
        a0.x += e0.w * v0.x; a0.y += e0.w * v0.y;
    }
    float2 bb = ((const float2*)bias)[lane];
    float lx = a0.x + a1.x + bb.x;
    float ly = a0.y + a1.y + bb.y;
    float m = fmaxf(lx, ly);
    #pragma unroll
    for (int o = 16; o > 0; o >>= 1)
        m = fmaxf(m, __shfl_xor_sync(0xFFFFFFFFu, m, o));
    float ex = __expf(lx - m), ey = __expf(ly - m);
    float s = ex + ey;
    #pragma unroll
    for (int o = 16; o > 0; o >>= 1)
        s += __shfl_xor_sync(0xFFFFFFFFu, s, o);
    float inv = 1.f / s;
    ((float2*)(out + (size_t)gw * NCLASS))[lane] = make_float2(ex * inv, ey * inv);
}

// ---------------- launch ----------------
extern "C" void kernel_launch(void* const* d_in, const int* in_sizes, int n_in,
                              void* d_out, int out_size) {
    const float* y    = (const float*)d_in[0];
    const void*  srcp = d_in[1];
    const void*  dstp = d_in[2];
    const float* ew   = (const float*)d_in[3];
    const float* W1   = (const float*)d_in[4];
    const float* b1   = (const float*)d_in[5];
    const float* W2   = (const float*)d_in[6];
    const float* b2   = (const float*)d_in[7];

    float* out_softmax = (float*)d_out;                              // [N, 64]
    float* out_emb     = (float*)d_out + (size_t)N_NODES * NCLASS;   // [N, 128]

    float* sup1; cudaGetSymbolAddress((void**)&sup1, g_support1);
    float* sup2; cudaGetSymbolAddress((void**)&sup2, g_support2);
    __half* b1h;
    __nv_bfloat16 *b2h, *b2l;
    cudaGetSymbolAddress((void**)&b1h, g_B1t_h);
    cudaGetSymbolAddress((void**)&b2h, g_B2t_h);
    cudaGetSymbolAddress((void**)&b2l, g_B2t_l);

    // smem: A hi/lo 2 stages (40960B) + B stages
    const int SMEM1 = 40960 + 20480;   // BN=128, B hi only (fp16 2-product)
    const int SMEM2 = 40960 + 20480;   // BN=64,  B hi+lo (bf16 3-product)
    static bool init_done = false;
    static cudaStream_t s2 = nullptr;
    static cudaEvent_t evFork = nullptr, evJoin = nullptr;
    if (!init_done) {
        cudaFuncSetAttribute(k_mma_gemm<NFEAT, NHID, true>,
                             cudaFuncAttributeMaxDynamicSharedMemorySize, SMEM1);
        cudaFuncSetAttribute(k_mma_gemm<NHID, NCLASS, false>,
                             cudaFuncAttributeMaxDynamicSharedMemorySize, SMEM2);
        cudaStreamCreateWithFlags(&s2, cudaStreamNonBlocking);
        cudaEventCreateWithFlags(&evFork, cudaEventDisableTiming);
        cudaEventCreateWithFlags(&evJoin, cudaEventDisableTiming);
        init_done = true;
    }

    // ---- fork: CSR build + W2 prep on side stream, hidden under GEMM1 ----
    cudaEventRecord(evFork, 0);
    cudaStreamWaitEvent(s2, evFork, 0);

    k_prepB<NHID, NCLASS><<<(NHID * NCLASS + 255) / 256, 256, 0, s2>>>(W2, b2h, b2l);
    k_detect<<<1, 1, 0, s2>>>(dstp);
    k_zero_cnt<<<(N_NODES + 255) / 256, 256, 0, s2>>>();
    k_count<<<(N_EDGES + 255) / 256, 256, 0, s2>>>(dstp);
    k_partsum<<<SCAN_BLOCKS, 1024, 0, s2>>>();
    k_scanpart<<<1, 128, 0, s2>>>();
    k_scanfinal<<<SCAN_BLOCKS, 1024, 0, s2>>>();
    k_scatter<<<(N_EDGES + 255) / 256, 256, 0, s2>>>(srcp, dstp, ew);
    cudaEventRecord(evJoin, s2);

    // ---- main stream: dense chain ----
    k_prepBh<NFEAT, NHID><<<(NFEAT * NHID + 255) / 256, 256>>>(W1, b1h);

    const int gblocks = (N_NODES + 127) / 128;
    k_mma_gemm<NFEAT, NHID, true><<<gblocks, 256, SMEM1>>>(y, b1h, b1h, sup1,
                                                           N_NODES);

    // ---- join: agg needs CSR ----
    cudaStreamWaitEvent(0, evJoin, 0);

    k_agg1<<<(N_NODES * 32 + 255) / 256, 256>>>(sup1, b1, out_emb);
    k_mma_gemm<NHID, NCLASS, false><<<gblocks, 256, SMEM2>>>(out_emb, b2h, b2l,
                                                             sup2, N_NODES);
    k_agg2<<<(N_NODES * 32 + 255) / 256, 256>>>(sup2, b2, out_softmax);
}

// round 9
// speedup vs baseline: 1.2954x; 1.0740x over previous
#include <cuda_runtime.h>
#include <cuda_bf16.h>
#include <cuda_fp16.h>
#include <cstdint>

#define N_NODES 100000
#define N_EDGES 1600000
#define NFEAT   512
#define NHID    128
#define NCLASS  64
#define SCAN_BLOCKS ((N_NODES + 1023) / 1024)   // 98

// ---------------- device scratch (no allocations allowed) ----------------
struct __align__(8) Edge { int s; float w; };

__device__ __half g_support1h[(size_t)N_NODES * NHID];   // y @ W1 (fp16)
__device__ float  g_support2[(size_t)N_NODES * NCLASS];  // h @ W2 (fp32)
__device__ int   g_cnt[N_NODES];
__device__ int   g_row_ptr[N_NODES + 1];
__device__ int   g_cursor[N_NODES + 1];
__device__ Edge  g_edges[N_EDGES];
__device__ int   g_idx64;
__device__ int   g_part[SCAN_BLOCKS];
__device__ int   g_partoff[SCAN_BLOCKS];
// W1 transposed, single fp16 (2-product split-A path)
__device__ __align__(16) __half        g_B1t_h[NHID * NFEAT];
// W2 transposed, split bf16 hi/lo (3-product path)
__device__ __align__(16) __nv_bfloat16 g_B2t_h[NCLASS * NHID];
__device__ __align__(16) __nv_bfloat16 g_B2t_l[NCLASS * NHID];

// ---------------- index dtype detection ----------------
__global__ void k_detect(const void* dst) {
    if (threadIdx.x == 0 && blockIdx.x == 0) {
        const unsigned long long* p = (const unsigned long long*)dst;
        int is64 = 1;
        #pragma unroll
        for (int i = 0; i < 8; i++)
            if (p[i] >= (unsigned long long)N_NODES) is64 = 0;
        g_idx64 = is64;
    }
}
__device__ __forceinline__ int load_idx(const void* p, int i, int is64) {
    return is64 ? (int)((const long long*)p)[i] : ((const int*)p)[i];
}

// ---------------- CSR build ----------------
__global__ void k_zero_cnt() {
    int i = blockIdx.x * blockDim.x + threadIdx.x;
    if (i < N_NODES) g_cnt[i] = 0;
}
__global__ void k_count(const void* dst) {
    int e = blockIdx.x * blockDim.x + threadIdx.x;
    if (e < N_EDGES) {
        int is64 = g_idx64;
        atomicAdd(&g_cnt[load_idx(dst, e, is64)], 1);
    }
}
__global__ void k_partsum() {
    int i = blockIdx.x * 1024 + threadIdx.x;
    int x = (i < N_NODES) ? g_cnt[i] : 0;
    #pragma unroll
    for (int o = 16; o > 0; o >>= 1) x += __shfl_xor_sync(0xFFFFFFFFu, x, o);
    __shared__ int ws[32];
    int lane = threadIdx.x & 31, w = threadIdx.x >> 5;
    if (lane == 0) ws[w] = x;
    __syncthreads();
    if (w == 0) {
        int v = ws[lane];
        #pragma unroll
        for (int o = 16; o > 0; o >>= 1) v += __shfl_xor_sync(0xFFFFFFFFu, v, o);
        if (lane == 0) g_part[blockIdx.x] = v;
    }
}
__global__ void k_scanpart() {
    __shared__ int s[128];
    int tid = threadIdx.x;
    int x = (tid < SCAN_BLOCKS) ? g_part[tid] : 0;
    s[tid] = x;
    __syncthreads();
    #pragma unroll
    for (int off = 1; off < 128; off <<= 1) {
        int t = (tid >= off) ? s[tid - off] : 0;
        __syncthreads();
        s[tid] += t;
        __syncthreads();
    }
    if (tid < SCAN_BLOCKS) g_partoff[tid] = s[tid] - x;
    if (tid == 127) g_row_ptr[N_NODES] = s[127];
}
__global__ void k_scanfinal() {
    __shared__ int warp_sums[32];
    int tid = threadIdx.x;
    int lane = tid & 31, w = tid >> 5;
    int i = blockIdx.x * 1024 + tid;
    int x = (i < N_NODES) ? g_cnt[i] : 0;
    int v = x;
    #pragma unroll
    for (int o = 1; o < 32; o <<= 1) {
        int t = __shfl_up_sync(0xFFFFFFFFu, v, o);
        if (lane >= o) v += t;
    }
    if (lane == 31) warp_sums[w] = v;
    __syncthreads();
    if (w == 0) {
        int s = warp_sums[lane];
        #pragma unroll
        for (int o = 1; o < 32; o <<= 1) {
            int t = __shfl_up_sync(0xFFFFFFFFu, s, o);
            if (lane >= o) s += t;
        }
        warp_sums[lane] = s;
    }
    __syncthreads();
    int excl = v - x + ((w == 0) ? 0 : warp_sums[w - 1]);
    if (i < N_NODES) {
        int val = g_partoff[blockIdx.x] + excl;
        g_row_ptr[i] = val;
        g_cursor[i]  = val;
    }
}
__global__ void k_scatter(const void* src, const void* dst,
                          const float* __restrict__ ew) {
    int e = blockIdx.x * blockDim.x + threadIdx.x;
    if (e < N_EDGES) {
        int is64 = g_idx64;
        int d = load_idx(dst, e, is64);
        int pos = atomicAdd(&g_cursor[d], 1);
        Edge ed; ed.s = load_idx(src, e, is64); ed.w = ew[e];
        g_edges[pos] = ed;
    }
}

// ---------------- weight prep ----------------
template <int K, int N>
__global__ void k_prepBh(const float* __restrict__ W,
                         __half* __restrict__ outh) {
    int t = blockIdx.x * blockDim.x + threadIdx.x;
    if (t < K * N) {
        int n = t / K, k = t % K;
        outh[t] = __float2half_rn(W[(size_t)k * N + n]);
    }
}
template <int K, int N>
__global__ void k_prepB(const float* __restrict__ W,
                        __nv_bfloat16* __restrict__ outh,
                        __nv_bfloat16* __restrict__ outl) {
    int t = blockIdx.x * blockDim.x + threadIdx.x;
    if (t < K * N) {
        int n = t / K, k = t % K;
        float v = W[(size_t)k * N + n];
        __nv_bfloat16 h = __float2bfloat16_rn(v);
        outh[t] = h;
        outl[t] = __float2bfloat16_rn(v - __bfloat162float(h));
    }
}

// ---------------- mixed-precision tensor-core GEMM, 1-sync pipeline -------
__device__ __forceinline__ void mma_bf16(float* c, const unsigned* a,
                                         const unsigned* b) {
    asm volatile(
        "mma.sync.aligned.m16n8k16.row.col.f32.bf16.bf16.f32 "
        "{%0,%1,%2,%3}, {%4,%5,%6,%7}, {%8,%9}, {%0,%1,%2,%3};\n"
        : "+f"(c[0]), "+f"(c[1]), "+f"(c[2]), "+f"(c[3])
        : "r"(a[0]), "r"(a[1]), "r"(a[2]), "r"(a[3]), "r"(b[0]), "r"(b[1]));
}
__device__ __forceinline__ void mma_f16(float* c, const unsigned* a,
                                        const unsigned* b) {
    asm volatile(
        "mma.sync.aligned.m16n8k16.row.col.f32.f16.f16.f32 "
        "{%0,%1,%2,%3}, {%4,%5,%6,%7}, {%8,%9}, {%0,%1,%2,%3};\n"
        : "+f"(c[0]), "+f"(c[1]), "+f"(c[2]), "+f"(c[3])
        : "r"(a[0]), "r"(a[1]), "r"(a[2]), "r"(a[3]), "r"(b[0]), "r"(b[1]));
}
#define LDSM_X4(r, a)                                                        \
    asm volatile("ldmatrix.sync.aligned.m8n8.x4.shared.b16 "                 \
                 "{%0,%1,%2,%3}, [%4];"                                      \
                 : "=r"((r)[0]), "=r"((r)[1]), "=r"((r)[2]), "=r"((r)[3])    \
                 : "r"(a))

// F16_2P=true : A split fp16 hi/lo, B single fp16 -> 2 MMA products
// F16_2P=false: A split bf16 hi/lo, B split bf16  -> 3 MMA products
// HALF_OUT: write C as fp16 (__half2 pairs).
template <int K, int BN, bool F16_2P, bool HALF_OUT>
__global__ __launch_bounds__(256, 2) void k_mma_gemm(
    const float* __restrict__ A,
    const void* __restrict__ Bhv,
    const void* __restrict__ Blv,
    void* __restrict__ Cv, int M) {
    constexpr int NWN = BN / 32;
    constexpr int NWM = 8 / NWN;
    constexpr int WTM = 128 / NWM;
    constexpr int MT  = WTM / 16;
    constexpr int KT  = K / 32;
    constexpr int A_ST = 128 * 20;
    constexpr int B_ST = BN * 20;

    const __nv_bfloat16* Bh = (const __nv_bfloat16*)Bhv;
    const __nv_bfloat16* Bl = (const __nv_bfloat16*)Blv;

    extern __shared__ char smem_raw[];
    unsigned* Ash = (unsigned*)smem_raw;                 // [2][A_ST]
    unsigned* Asl = Ash + 2 * A_ST;
    unsigned* Bsh = Asl + 2 * A_ST;                      // [2][B_ST]
    unsigned* Bsl = Bsh + 2 * B_ST;                      // only if !F16_2P

    const int tid = threadIdx.x;
    const int wid = tid >> 5, lane = tid & 31;
    const int wm = wid / NWN, wn = wid % NWN;
    const int gid = lane >> 2, t4 = lane & 3;
    const int bm0 = blockIdx.x * 128;

    unsigned sBh = (unsigned)__cvta_generic_to_shared(Bsh);
    unsigned sBl = (unsigned)__cvta_generic_to_shared(Bsl);

    const int rowA = wm * WTM + (lane & 7) + ((lane >> 3) & 1) * 8;
    const int colA = ((lane >> 4) & 1) * 4;
    const unsigned aOff = (unsigned)(rowA * 20 + colA) * 4u;
    const unsigned aAddrH = (unsigned)__cvta_generic_to_shared(Ash) + aOff;
    const unsigned aAddrL = (unsigned)__cvta_generic_to_shared(Asl) + aOff;
    const int rowB = wn * 32 + (lane & 7) + ((lane >> 4) & 1) * 8;
    const int colB = ((lane >> 3) & 1) * 4;
    const unsigned bOff = (unsigned)(rowB * 20 + colB) * 4u;
    const unsigned bAddrH = sBh + bOff;
    const unsigned bAddrL = sBl + bOff;

    float4 areg[4];
    auto ldgA = [&](int kt) {
        int k0 = kt * 32;
        #pragma unroll
        for (int i = 0; i < 4; i++) {
            int linear = tid + 256 * i;
            int row = linear >> 3, c4 = linear & 7;
            int gr = bm0 + row;
            areg[i] = (gr < M)
                ? *(const float4*)(A + (size_t)gr * K + k0 + c4 * 4)
                : make_float4(0.f, 0.f, 0.f, 0.f);
        }
    };
    auto stsA = [&](int st) {
        #pragma unroll
        for (int i = 0; i < 4; i++) {
            int linear = tid + 256 * i;
            int row = linear >> 3, c4 = linear & 7;
            float f[4] = {areg[i].x, areg[i].y, areg[i].z, areg[i].w};
            unsigned short hh[4], ll[4];
            #pragma unroll
            for (int c = 0; c < 4; c++) {
                if (F16_2P) {
                    __half h = __float2half_rn(f[c]);
                    __half l = __float2half_rn(f[c] - __half2float(h));
                    hh[c] = __half_as_ushort(h);
                    ll[c] = __half_as_ushort(l);
                } else {
                    __nv_bfloat16 h = __float2bfloat16_rn(f[c]);
                    __nv_bfloat16 l =
                        __float2bfloat16_rn(f[c] - __bfloat162float(h));
                    hh[c] = __bfloat16_as_ushort(h);
                    ll[c] = __bfloat16_as_ushort(l);
                }
            }
            uint2 ph = make_uint2((unsigned)hh[0] | ((unsigned)hh[1] << 16),
                                  (unsigned)hh[2] | ((unsigned)hh[3] << 16));
            uint2 pl = make_uint2((unsigned)ll[0] | ((unsigned)ll[1] << 16),
                                  (unsigned)ll[2] | ((unsigned)ll[3] << 16));
            *(uint2*)&Ash[st * A_ST + row * 20 + c4 * 2] = ph;
            *(uint2*)&Asl[st * A_ST + row * 20 + c4 * 2] = pl;
        }
    };
    auto cpB = [&](int kt, int st) {
        int k0 = kt * 32;
        constexpr int BI = (BN * 4) / 256;
        #pragma unroll
        for (int i = 0; i < BI; i++) {
            int linear = tid + 256 * i;
            int row = linear >> 2, j = linear & 3;
            unsigned dh = sBh + (st * B_ST + row * 20 + j * 4) * 4;
            const __nv_bfloat16* ph = Bh + (size_t)row * K + k0 + j * 8;
            asm volatile("cp.async.ca.shared.global [%0], [%1], 16;\n" :: "r"(dh), "l"(ph));
            if (!F16_2P) {
                unsigned dl = sBl + (st * B_ST + row * 20 + j * 4) * 4;
                const __nv_bfloat16* pl = Bl + (size_t)row * K + k0 + j * 8;
                asm volatile("cp.async.ca.shared.global [%0], [%1], 16;\n" :: "r"(dl), "l"(pl));
            }
        }
        asm volatile("cp.async.commit_group;\n");
    };

    float acc[MT][4][4];
    #pragma unroll
    for (int m = 0; m < MT; m++)
        #pragma unroll
        for (int n = 0; n < 4; n++)
            #pragma unroll
            for (int r = 0; r < 4; r++) acc[m][n][r] = 0.f;

    ldgA(0);
    cpB(0, 0);
    stsA(0);
    if (KT > 1) ldgA(1);

    for (int kt = 0; kt < KT; kt++) {
        const int st = kt & 1;
        asm volatile("cp.async.wait_group 0;\n");
        __syncthreads();

        if (kt + 1 < KT) cpB(kt + 1, st ^ 1);

        const unsigned aStOff = (unsigned)(st * A_ST) * 4u;
        const unsigned bStOff = (unsigned)(st * B_ST) * 4u;
        #pragma unroll
        for (int kk = 0; kk < 2; kk++) {
            const unsigned kOff = (unsigned)(kk * 8) * 4u;
            unsigned bh[2][4], bl[2][4];
            #pragma unroll
            for (int p = 0; p < 2; p++) {
                unsigned po = (unsigned)(p * 16 * 20) * 4u;
                LDSM_X4(bh[p], bAddrH + bStOff + kOff + po);
                if (!F16_2P) LDSM_X4(bl[p], bAddrL + bStOff + kOff + po);
            }
            #pragma unroll
            for (int mt = 0; mt < MT; mt++) {
                unsigned mo = (unsigned)(mt * 16 * 20) * 4u;
                unsigned ah[4], al[4];
                LDSM_X4(ah, aAddrH + aStOff + kOff + mo);
                LDSM_X4(al, aAddrL + aStOff + kOff + mo);
                #pragma unroll
                for (int nt = 0; nt < 4; nt++) {
                    const unsigned* bhp = &bh[nt >> 1][(nt & 1) * 2];
                    if (F16_2P) {
                        mma_f16(acc[mt][nt], ah, bhp);
                        mma_f16(acc[mt][nt], al, bhp);
                    } else {
                        const unsigned* blp = &bl[nt >> 1][(nt & 1) * 2];
                        mma_bf16(acc[mt][nt], ah, bhp);
                        mma_bf16(acc[mt][nt], ah, blp);
                        mma_bf16(acc[mt][nt], al, bhp);
                    }
                }
            }
        }
        if (kt + 1 < KT) {
            stsA(st ^ 1);
            if (kt + 2 < KT) ldgA(kt + 2);
        }
    }

    // ---- epilogue ----
    #pragma unroll
    for (int mt = 0; mt < MT; mt++) {
        int r = bm0 + wm * WTM + mt * 16 + gid;
        #pragma unroll
        for (int nt = 0; nt < 4; nt++) {
            int c = wn * 32 + nt * 8 + 2 * t4;
            if (HALF_OUT) {
                __half2* C2 = (__half2*)Cv;
                if (r < M)
                    C2[((size_t)r * BN + c) >> 1] =
                        __floats2half2_rn(acc[mt][nt][0], acc[mt][nt][1]);
                if (r + 8 < M)
                    C2[((size_t)(r + 8) * BN + c) >> 1] =
                        __floats2half2_rn(acc[mt][nt][2], acc[mt][nt][3]);
            } else {
                float* C = (float*)Cv;
                if (r < M)
                    *(float2*)&C[(size_t)r * BN + c] =
                        make_float2(acc[mt][nt][0], acc[mt][nt][1]);
                if (r + 8 < M)
                    *(float2*)&C[(size_t)(r + 8) * BN + c] =
                        make_float2(acc[mt][nt][2], acc[mt][nt][3]);
            }
        }
    }
}

// ----- layer-1 aggregation: fp16 sup1 gather, fp32 accum, bias+leaky -----
__global__ void k_agg1(const __half2* __restrict__ sup,   // [N][64] __half2
                       const float* __restrict__ bias,
                       float* __restrict__ h) {
    int gw = (blockIdx.x * blockDim.x + threadIdx.x) >> 5;
    if (gw >= N_NODES) return;
    int lane = threadIdx.x & 31;
    int beg = g_row_ptr[gw], end = g_row_ptr[gw + 1];
    float4 a0 = make_float4(0.f, 0.f, 0.f, 0.f);
    float4 a1 = make_float4(0.f, 0.f, 0.f, 0.f);
    int e = beg;
    for (; e + 2 <= end; e += 2) {
        Edge e0 = g_edges[e], e1 = g_edges[e + 1];
        // lane loads 2 consecutive __half2 (8B) -> 4 features
        const __half2* r0 = sup + (size_t)e0.s * 64 + lane * 2;
        const __half2* r1 = sup + (size_t)e1.s * 64 + lane * 2;
        __half2 p00 = r0[0], p01 = r0[1];
        __half2 p10 = r1[0], p11 = r1[1];
        float2 f00 = __half22float2(p00), f01 = __half22float2(p01);
        float2 f10 = __half22float2(p10), f11 = __half22float2(p11);
        a0.x += e0.w * f00.x; a0.y += e0.w * f00.y;
        a0.z += e0.w * f01.x; a0.w += e0.w * f01.y;
        a1.x += e1.w * f10.x; a1.y += e1.w * f10.y;
        a1.z += e1.w * f11.x; a1.w += e1.w * f11.y;
    }
    if (e < end) {
        Edge e0 = g_edges[e];
        const __half2* r0 = sup + (size_t)e0.s * 64 + lane * 2;
        float2 f00 = __half22float2(r0[0]), f01 = __half22float2(r0[1]);
        a0.x += e0.w * f00.x; a0.y += e0.w * f00.y;
        a0.z += e0.w * f01.x; a0.w += e0.w * f01.y;
    }
    // lane owns features [lane*4 .. lane*4+3]
    float4 bb = ((const float4*)bias)[lane];
    float4 r;
    r.x = a0.x + a1.x + bb.x;
    r.y = a0.y + a1.y + bb.y;
    r.z = a0.z + a1.z + bb.z;
    r.w = a0.w + a1.w + bb.w;
    r.x = r.x > 0.f ? r.x : 0.01f * r.x;
    r.y = r.y > 0.f ? r.y : 0.01f * r.y;
    r.z = r.z > 0.f ? r.z : 0.01f * r.z;
    r.w = r.w > 0.f ? r.w : 0.01f * r.w;
    ((float4*)(h + (size_t)gw * NHID))[lane] = r;
}

// ------- layer-2 aggregation: warp per node, fused bias + softmax --------
__global__ void k_agg2(const float* __restrict__ sup,
                       const float* __restrict__ bias,
                       float* __restrict__ out) {
    int gw = (blockIdx.x * blockDim.x + threadIdx.x) >> 5;
    if (gw >= N_NODES) return;
    int lane = threadIdx.x & 31;
    int beg = g_row_ptr[gw], end = g_row_ptr[gw + 1];
    float2 a0 = make_float2(0.f, 0.f);
    float2 a1 = make_float2(0.f, 0.f);
    int e = beg;
    for (; e + 2 <= end; e += 2) {
        Edge e0 = g_edges[e], e1 = g_edges[e + 1];
        float2 v0 = ((const float2*)(sup + (size_t)e0.s * NCLASS))[lane];
        float2 v1 = ((const float2*)(sup + (size_t)e1.s * NCLASS))[lane];
        a0.x += e0.w * v0.x; a0.y += e0.w * v0.y;
        a1.x += e1.w * v1.x; a1.y += e1.w * v1.y;
    }
    if (e < end) {
        Edge e0 = g_edges[e];
        float2 v0 = ((const float2*)(sup + (size_t)e0.s * NCLASS))[lane];
        a0.x += e0.w * v0.x; a0.y += e0.w * v0.y;
    }
    float2 bb = ((const float2*)bias)[lane];
    float lx = a0.x + a1.x + bb.x;
    float ly = a0.y + a1.y + bb.y;
    float m = fmaxf(lx, ly);
    #pragma unroll
    for (int o = 16; o > 0; o >>= 1)
        m = fmaxf(m, __shfl_xor_sync(0xFFFFFFFFu, m, o));
    float ex = __expf(lx - m), ey = __expf(ly - m);
    float s = ex + ey;
    #pragma unroll
    for (int o = 16; o > 0; o >>= 1)
        s += __shfl_xor_sync(0xFFFFFFFFu, s, o);
    float inv = 1.f / s;
    ((float2*)(out + (size_t)gw * NCLASS))[lane] = make_float2(ex * inv, ey * inv);
}

// ---------------- launch ----------------
extern "C" void kernel_launch(void* const* d_in, const int* in_sizes, int n_in,
                              void* d_out, int out_size) {
    const float* y    = (const float*)d_in[0];
    const void*  srcp = d_in[1];
    const void*  dstp = d_in[2];
    const float* ew   = (const float*)d_in[3];
    const float* W1   = (const float*)d_in[4];
    const float* b1   = (const float*)d_in[5];
    const float* W2   = (const float*)d_in[6];
    const float* b2   = (const float*)d_in[7];

    float* out_softmax = (float*)d_out;                              // [N, 64]
    float* out_emb     = (float*)d_out + (size_t)N_NODES * NCLASS;   // [N, 128]

    __half* sup1h; cudaGetSymbolAddress((void**)&sup1h, g_support1h);
    float*  sup2;  cudaGetSymbolAddress((void**)&sup2, g_support2);
    __half* b1h;
    __nv_bfloat16 *b2h, *b2l;
    cudaGetSymbolAddress((void**)&b1h, g_B1t_h);
    cudaGetSymbolAddress((void**)&b2h, g_B2t_h);
    cudaGetSymbolAddress((void**)&b2l, g_B2t_l);

    const int SMEM1 = 40960 + 20480;   // BN=128, B hi only (fp16 2-product)
    const int SMEM2 = 40960 + 20480;   // BN=64,  B hi+lo (bf16 3-product)
    static bool init_done = false;
    static cudaStream_t s2 = nullptr;
    static cudaEvent_t evFork = nullptr, evJoin = nullptr;
    if (!init_done) {
        cudaFuncSetAttribute(k_mma_gemm<NFEAT, NHID, true, true>,
                             cudaFuncAttributeMaxDynamicSharedMemorySize, SMEM1);
        cudaFuncSetAttribute(k_mma_gemm<NHID, NCLASS, false, false>,
                             cudaFuncAttributeMaxDynamicSharedMemorySize, SMEM2);
        cudaStreamCreateWithFlags(&s2, cudaStreamNonBlocking);
        cudaEventCreateWithFlags(&evFork, cudaEventDisableTiming);
        cudaEventCreateWithFlags(&evJoin, cudaEventDisableTiming);
        init_done = true;
    }

    // ---- fork: CSR build + W2 prep on side stream, hidden under GEMM1 ----
    cudaEventRecord(evFork, 0);
    cudaStreamWaitEvent(s2, evFork, 0);

    k_prepB<NHID, NCLASS><<<(NHID * NCLASS + 255) / 256, 256, 0, s2>>>(W2, b2h, b2l);
    k_detect<<<1, 1, 0, s2>>>(dstp);
    k_zero_cnt<<<(N_NODES + 255) / 256, 256, 0, s2>>>();
    k_count<<<(N_EDGES + 255) / 256, 256, 0, s2>>>(dstp);
    k_partsum<<<SCAN_BLOCKS, 1024, 0, s2>>>();
    k_scanpart<<<1, 128, 0, s2>>>();
    k_scanfinal<<<SCAN_BLOCKS, 1024, 0, s2>>>();
    k_scatter<<<(N_EDGES + 255) / 256, 256, 0, s2>>>(srcp, dstp, ew);
    cudaEventRecord(evJoin, s2);

    // ---- main stream: dense chain ----
    k_prepBh<NFEAT, NHID><<<(NFEAT * NHID + 255) / 256, 256>>>(W1, b1h);

    const int gblocks = (N_NODES + 127) / 128;
    k_mma_gemm<NFEAT, NHID, true, true><<<gblocks, 256, SMEM1>>>(
        y, b1h, b1h, sup1h, N_NODES);

    // ---- join: agg needs CSR ----
    cudaStreamWaitEvent(0, evJoin, 0);

    k_agg1<<<(N_NODES * 32 + 255) / 256, 256>>>((const __half2*)sup1h, b1,
                                                out_emb);
    k_mma_gemm<NHID, NCLASS, false, false><<<gblocks, 256, SMEM2>>>(
        out_emb, b2h, b2l, sup2, N_NODES);
    k_agg2<<<(N_NODES * 32 + 255) / 256, 256>>>(sup2, b2, out_softmax);
}

// round 10
// speedup vs baseline: 1.3435x; 1.0371x over previous
#include <cuda_runtime.h>
#include <cuda_bf16.h>
#include <cuda_fp16.h>
#include <cstdint>

#define N_NODES 100000
#define N_EDGES 1600000
#define NFEAT   512
#define NHID    128
#define NCLASS  64
#define SCAN_BLOCKS ((N_NODES + 1023) / 1024)   // 98

// ---------------- device scratch (no allocations allowed) ----------------
struct __align__(8) Edge { int s; float w; };

__device__ __half g_support1h[(size_t)N_NODES * NHID];   // y @ W1 (fp16)
__device__ __half g_support2h[(size_t)N_NODES * NCLASS]; // h @ W2 (fp16)
__device__ int   g_cnt[N_NODES];
__device__ int   g_row_ptr[N_NODES + 1];
__device__ int   g_cursor[N_NODES + 1];
__device__ Edge  g_edges[N_EDGES];
__device__ int   g_idx64;
__device__ int   g_part[SCAN_BLOCKS];
__device__ int   g_partoff[SCAN_BLOCKS];
// W1 transposed, single fp16 (2-product split-A path)
__device__ __align__(16) __half        g_B1t_h[NHID * NFEAT];
// W2 transposed, split bf16 hi/lo (3-product path)
__device__ __align__(16) __nv_bfloat16 g_B2t_h[NCLASS * NHID];
__device__ __align__(16) __nv_bfloat16 g_B2t_l[NCLASS * NHID];

// ---------------- index dtype detection ----------------
__global__ void k_detect(const void* dst) {
    if (threadIdx.x == 0 && blockIdx.x == 0) {
        const unsigned long long* p = (const unsigned long long*)dst;
        int is64 = 1;
        #pragma unroll
        for (int i = 0; i < 8; i++)
            if (p[i] >= (unsigned long long)N_NODES) is64 = 0;
        g_idx64 = is64;
    }
}
__device__ __forceinline__ int load_idx(const void* p, int i, int is64) {
    return is64 ? (int)((const long long*)p)[i] : ((const int*)p)[i];
}

// ---------------- CSR build ----------------
__global__ void k_zero_cnt() {
    int i = blockIdx.x * blockDim.x + threadIdx.x;
    if (i < N_NODES) g_cnt[i] = 0;
}
__global__ void k_count(const void* dst) {
    int e = blockIdx.x * blockDim.x + threadIdx.x;
    if (e < N_EDGES) {
        int is64 = g_idx64;
        atomicAdd(&g_cnt[load_idx(dst, e, is64)], 1);
    }
}
__global__ void k_partsum() {
    int i = blockIdx.x * 1024 + threadIdx.x;
    int x = (i < N_NODES) ? g_cnt[i] : 0;
    #pragma unroll
    for (int o = 16; o > 0; o >>= 1) x += __shfl_xor_sync(0xFFFFFFFFu, x, o);
    __shared__ int ws[32];
    int lane = threadIdx.x & 31, w = threadIdx.x >> 5;
    if (lane == 0) ws[w] = x;
    __syncthreads();
    if (w == 0) {
        int v = ws[lane];
        #pragma unroll
        for (int o = 16; o > 0; o >>= 1) v += __shfl_xor_sync(0xFFFFFFFFu, v, o);
        if (lane == 0) g_part[blockIdx.x] = v;
    }
}
__global__ void k_scanpart() {
    __shared__ int s[128];
    int tid = threadIdx.x;
    int x = (tid < SCAN_BLOCKS) ? g_part[tid] : 0;
    s[tid] = x;
    __syncthreads();
    #pragma unroll
    for (int off = 1; off < 128; off <<= 1) {
        int t = (tid >= off) ? s[tid - off] : 0;
        __syncthreads();
        s[tid] += t;
        __syncthreads();
    }
    if (tid < SCAN_BLOCKS) g_partoff[tid] = s[tid] - x;
    if (tid == 127) g_row_ptr[N_NODES] = s[127];
}
__global__ void k_scanfinal() {
    __shared__ int warp_sums[32];
    int tid = threadIdx.x;
    int lane = tid & 31, w = tid >> 5;
    int i = blockIdx.x * 1024 + tid;
    int x = (i < N_NODES) ? g_cnt[i] : 0;
    int v = x;
    #pragma unroll
    for (int o = 1; o < 32; o <<= 1) {
        int t = __shfl_up_sync(0xFFFFFFFFu, v, o);
        if (lane >= o) v += t;
    }
    if (lane == 31) warp_sums[w] = v;
    __syncthreads();
    if (w == 0) {
        int s = warp_sums[lane];
        #pragma unroll
        for (int o = 1; o < 32; o <<= 1) {
            int t = __shfl_up_sync(0xFFFFFFFFu, s, o);
            if (lane >= o) s += t;
        }
        warp_sums[lane] = s;
    }
    __syncthreads();
    int excl = v - x + ((w == 0) ? 0 : warp_sums[w - 1]);
    if (i < N_NODES) {
        int val = g_partoff[blockIdx.x] + excl;
        g_row_ptr[i] = val;
        g_cursor[i]  = val;
    }
}
__global__ void k_scatter(const void* src, const void* dst,
                          const float* __restrict__ ew) {
    int e = blockIdx.x * blockDim.x + threadIdx.x;
    if (e < N_EDGES) {
        int is64 = g_idx64;
        int d = load_idx(dst, e, is64);
        int pos = atomicAdd(&g_cursor[d], 1);
        Edge ed; ed.s = load_idx(src, e, is64); ed.w = ew[e];
        g_edges[pos] = ed;
    }
}

// ---------------- weight prep ----------------
template <int K, int N>
__global__ void k_prepBh(const float* __restrict__ W,
                         __half* __restrict__ outh) {
    int t = blockIdx.x * blockDim.x + threadIdx.x;
    if (t < K * N) {
        int n = t / K, k = t % K;
        outh[t] = __float2half_rn(W[(size_t)k * N + n]);
    }
}
template <int K, int N>
__global__ void k_prepB(const float* __restrict__ W,
                        __nv_bfloat16* __restrict__ outh,
                        __nv_bfloat16* __restrict__ outl) {
    int t = blockIdx.x * blockDim.x + threadIdx.x;
    if (t < K * N) {
        int n = t / K, k = t % K;
        float v = W[(size_t)k * N + n];
        __nv_bfloat16 h = __float2bfloat16_rn(v);
        outh[t] = h;
        outl[t] = __float2bfloat16_rn(v - __bfloat162float(h));
    }
}

// ---------------- mixed-precision tensor-core GEMM, 1-sync pipeline -------
__device__ __forceinline__ void mma_bf16(float* c, const unsigned* a,
                                         const unsigned* b) {
    asm volatile(
        "mma.sync.aligned.m16n8k16.row.col.f32.bf16.bf16.f32 "
        "{%0,%1,%2,%3}, {%4,%5,%6,%7}, {%8,%9}, {%0,%1,%2,%3};\n"
        : "+f"(c[0]), "+f"(c[1]), "+f"(c[2]), "+f"(c[3])
        : "r"(a[0]), "r"(a[1]), "r"(a[2]), "r"(a[3]), "r"(b[0]), "r"(b[1]));
}
__device__ __forceinline__ void mma_f16(float* c, const unsigned* a,
                                        const unsigned* b) {
    asm volatile(
        "mma.sync.aligned.m16n8k16.row.col.f32.f16.f16.f32 "
        "{%0,%1,%2,%3}, {%4,%5,%6,%7}, {%8,%9}, {%0,%1,%2,%3};\n"
        : "+f"(c[0]), "+f"(c[1]), "+f"(c[2]), "+f"(c[3])
        : "r"(a[0]), "r"(a[1]), "r"(a[2]), "r"(a[3]), "r"(b[0]), "r"(b[1]));
}
#define LDSM_X4(r, a)                                                        \
    asm volatile("ldmatrix.sync.aligned.m8n8.x4.shared.b16 "                 \
                 "{%0,%1,%2,%3}, [%4];"                                      \
                 : "=r"((r)[0]), "=r"((r)[1]), "=r"((r)[2]), "=r"((r)[3])    \
                 : "r"(a))

// F16_2P=true : A split fp16 hi/lo, B single fp16 -> 2 MMA products
// F16_2P=false: A split bf16 hi/lo, B split bf16  -> 3 MMA products
// HALF_OUT: write C as fp16 (__half2 pairs).
template <int K, int BN, bool F16_2P, bool HALF_OUT>
__global__ __launch_bounds__(256, 2) void k_mma_gemm(
    const float* __restrict__ A,
    const void* __restrict__ Bhv,
    const void* __restrict__ Blv,
    void* __restrict__ Cv, int M) {
    constexpr int NWN = BN / 32;
    constexpr int NWM = 8 / NWN;
    constexpr int WTM = 128 / NWM;
    constexpr int MT  = WTM / 16;
    constexpr int KT  = K / 32;
    constexpr int A_ST = 128 * 20;
    constexpr int B_ST = BN * 20;

    const __nv_bfloat16* Bh = (const __nv_bfloat16*)Bhv;
    const __nv_bfloat16* Bl = (const __nv_bfloat16*)Blv;

    extern __shared__ char smem_raw[];
    unsigned* Ash = (unsigned*)smem_raw;                 // [2][A_ST]
    unsigned* Asl = Ash + 2 * A_ST;
    unsigned* Bsh = Asl + 2 * A_ST;                      // [2][B_ST]
    unsigned* Bsl = Bsh + 2 * B_ST;                      // only if !F16_2P

    const int tid = threadIdx.x;
    const int wid = tid >> 5, lane = tid & 31;
    const int wm = wid / NWN, wn = wid % NWN;
    const int gid = lane >> 2, t4 = lane & 3;
    const int bm0 = blockIdx.x * 128;

    unsigned sBh = (unsigned)__cvta_generic_to_shared(Bsh);
    unsigned sBl = (unsigned)__cvta_generic_to_shared(Bsl);

    const int rowA = wm * WTM + (lane & 7) + ((lane >> 3) & 1) * 8;
    const int colA = ((lane >> 4) & 1) * 4;
    const unsigned aOff = (unsigned)(rowA * 20 + colA) * 4u;
    const unsigned aAddrH = (unsigned)__cvta_generic_to_shared(Ash) + aOff;
    const unsigned aAddrL = (unsigned)__cvta_generic_to_shared(Asl) + aOff;
    const int rowB = wn * 32 + (lane & 7) + ((lane >> 4) & 1) * 8;
    const int colB = ((lane >> 3) & 1) * 4;
    const unsigned bOff = (unsigned)(rowB * 20 + colB) * 4u;
    const unsigned bAddrH = sBh + bOff;
    const unsigned bAddrL = sBl + bOff;

    float4 areg[4];
    auto ldgA = [&](int kt) {
        int k0 = kt * 32;
        #pragma unroll
        for (int i = 0; i < 4; i++) {
            int linear = tid + 256 * i;
            int row = linear >> 3, c4 = linear & 7;
            int gr = bm0 + row;
            areg[i] = (gr < M)
                ? *(const float4*)(A + (size_t)gr * K + k0 + c4 * 4)
                : make_float4(0.f, 0.f, 0.f, 0.f);
        }
    };
    auto stsA = [&](int st) {
        #pragma unroll
        for (int i = 0; i < 4; i++) {
            int linear = tid + 256 * i;
            int row = linear >> 3, c4 = linear & 7;
            float f[4] = {areg[i].x, areg[i].y, areg[i].z, areg[i].w};
            unsigned short hh[4], ll[4];
            #pragma unroll
            for (int c = 0; c < 4; c++) {
                if (F16_2P) {
                    __half h = __float2half_rn(f[c]);
                    __half l = __float2half_rn(f[c] - __half2float(h));
                    hh[c] = __half_as_ushort(h);
                    ll[c] = __half_as_ushort(l);
                } else {
                    __nv_bfloat16 h = __float2bfloat16_rn(f[c]);
                    __nv_bfloat16 l =
                        __float2bfloat16_rn(f[c] - __bfloat162float(h));
                    hh[c] = __bfloat16_as_ushort(h);
                    ll[c] = __bfloat16_as_ushort(l);
                }
            }
            uint2 ph = make_uint2((unsigned)hh[0] | ((unsigned)hh[1] << 16),
                                  (unsigned)hh[2] | ((unsigned)hh[3] << 16));
            uint2 pl = make_uint2((unsigned)ll[0] | ((unsigned)ll[1] << 16),
                                  (unsigned)ll[2] | ((unsigned)ll[3] << 16));
            *(uint2*)&Ash[st * A_ST + row * 20 + c4 * 2] = ph;
            *(uint2*)&Asl[st * A_ST + row * 20 + c4 * 2] = pl;
        }
    };
    auto cpB = [&](int kt, int st) {
        int k0 = kt * 32;
        constexpr int BI = (BN * 4) / 256;
        #pragma unroll
        for (int i = 0; i < BI; i++) {
            int linear = tid + 256 * i;
            int row = linear >> 2, j = linear & 3;
            unsigned dh = sBh + (st * B_ST + row * 20 + j * 4) * 4;
            const __nv_bfloat16* ph = Bh + (size_t)row * K + k0 + j * 8;
            asm volatile("cp.async.ca.shared.global [%0], [%1], 16;\n" :: "r"(dh), "l"(ph));
            if (!F16_2P) {
                unsigned dl = sBl + (st * B_ST + row * 20 + j * 4) * 4;
                const __nv_bfloat16* pl = Bl + (size_t)row * K + k0 + j * 8;
                asm volatile("cp.async.ca.shared.global [%0], [%1], 16;\n" :: "r"(dl), "l"(pl));
            }
        }
        asm volatile("cp.async.commit_group;\n");
    };

    float acc[MT][4][4];
    #pragma unroll
    for (int m = 0; m < MT; m++)
        #pragma unroll
        for (int n = 0; n < 4; n++)
            #pragma unroll
            for (int r = 0; r < 4; r++) acc[m][n][r] = 0.f;

    ldgA(0);
    cpB(0, 0);
    stsA(0);
    if (KT > 1) ldgA(1);

    for (int kt = 0; kt < KT; kt++) {
        const int st = kt & 1;
        asm volatile("cp.async.wait_group 0;\n");
        __syncthreads();

        if (kt + 1 < KT) cpB(kt + 1, st ^ 1);

        const unsigned aStOff = (unsigned)(st * A_ST) * 4u;
        const unsigned bStOff = (unsigned)(st * B_ST) * 4u;
        #pragma unroll
        for (int kk = 0; kk < 2; kk++) {
            const unsigned kOff = (unsigned)(kk * 8) * 4u;
            unsigned bh[2][4], bl[2][4];
            #pragma unroll
            for (int p = 0; p < 2; p++) {
                unsigned po = (unsigned)(p * 16 * 20) * 4u;
                LDSM_X4(bh[p], bAddrH + bStOff + kOff + po);
                if (!F16_2P) LDSM_X4(bl[p], bAddrL + bStOff + kOff + po);
            }
            #pragma unroll
            for (int mt = 0; mt < MT; mt++) {
                unsigned mo = (unsigned)(mt * 16 * 20) * 4u;
                unsigned ah[4], al[4];
                LDSM_X4(ah, aAddrH + aStOff + kOff + mo);
                LDSM_X4(al, aAddrL + aStOff + kOff + mo);
                #pragma unroll
                for (int nt = 0; nt < 4; nt++) {
                    const unsigned* bhp = &bh[nt >> 1][(nt & 1) * 2];
                    if (F16_2P) {
                        mma_f16(acc[mt][nt], ah, bhp);
                        mma_f16(acc[mt][nt], al, bhp);
                    } else {
                        const unsigned* blp = &bl[nt >> 1][(nt & 1) * 2];
                        mma_bf16(acc[mt][nt], ah, bhp);
                        mma_bf16(acc[mt][nt], ah, blp);
                        mma_bf16(acc[mt][nt], al, bhp);
                    }
                }
            }
        }
        if (kt + 1 < KT) {
            stsA(st ^ 1);
            if (kt + 2 < KT) ldgA(kt + 2);
        }
    }

    // ---- epilogue ----
    #pragma unroll
    for (int mt = 0; mt < MT; mt++) {
        int r = bm0 + wm * WTM + mt * 16 + gid;
        #pragma unroll
        for (int nt = 0; nt < 4; nt++) {
            int c = wn * 32 + nt * 8 + 2 * t4;
            if (HALF_OUT) {
                __half2* C2 = (__half2*)Cv;
                if (r < M)
                    C2[((size_t)r * BN + c) >> 1] =
                        __floats2half2_rn(acc[mt][nt][0], acc[mt][nt][1]);
                if (r + 8 < M)
                    C2[((size_t)(r + 8) * BN + c) >> 1] =
                        __floats2half2_rn(acc[mt][nt][2], acc[mt][nt][3]);
            } else {
                float* C = (float*)Cv;
                if (r < M)
                    *(float2*)&C[(size_t)r * BN + c] =
                        make_float2(acc[mt][nt][0], acc[mt][nt][1]);
                if (r + 8 < M)
                    *(float2*)&C[(size_t)(r + 8) * BN + c] =
                        make_float2(acc[mt][nt][2], acc[mt][nt][3]);
            }
        }
    }
}

// ----- layer-1 aggregation: fp16 sup1 gather, fp32 accum, bias+leaky -----
__global__ void k_agg1(const __half2* __restrict__ sup,   // [N][64] __half2
                       const float* __restrict__ bias,
                       float* __restrict__ h) {
    int gw = (blockIdx.x * blockDim.x + threadIdx.x) >> 5;
    if (gw >= N_NODES) return;
    int lane = threadIdx.x & 31;
    int beg = g_row_ptr[gw], end = g_row_ptr[gw + 1];
    float4 a0 = make_float4(0.f, 0.f, 0.f, 0.f);
    float4 a1 = make_float4(0.f, 0.f, 0.f, 0.f);
    int e = beg;
    for (; e + 2 <= end; e += 2) {
        Edge e0 = g_edges[e], e1 = g_edges[e + 1];
        const __half2* r0 = sup + (size_t)e0.s * 64 + lane * 2;
        const __half2* r1 = sup + (size_t)e1.s * 64 + lane * 2;
        __half2 p00 = r0[0], p01 = r0[1];
        __half2 p10 = r1[0], p11 = r1[1];
        float2 f00 = __half22float2(p00), f01 = __half22float2(p01);
        float2 f10 = __half22float2(p10), f11 = __half22float2(p11);
        a0.x += e0.w * f00.x; a0.y += e0.w * f00.y;
        a0.z += e0.w * f01.x; a0.w += e0.w * f01.y;
        a1.x += e1.w * f10.x; a1.y += e1.w * f10.y;
        a1.z += e1.w * f11.x; a1.w += e1.w * f11.y;
    }
    if (e < end) {
        Edge e0 = g_edges[e];
        const __half2* r0 = sup + (size_t)e0.s * 64 + lane * 2;
        float2 f00 = __half22float2(r0[0]), f01 = __half22float2(r0[1]);
        a0.x += e0.w * f00.x; a0.y += e0.w * f00.y;
        a0.z += e0.w * f01.x; a0.w += e0.w * f01.y;
    }
    float4 bb = ((const float4*)bias)[lane];
    float4 r;
    r.x = a0.x + a1.x + bb.x;
    r.y = a0.y + a1.y + bb.y;
    r.z = a0.z + a1.z + bb.z;
    r.w = a0.w + a1.w + bb.w;
    r.x = r.x > 0.f ? r.x : 0.01f * r.x;
    r.y = r.y > 0.f ? r.y : 0.01f * r.y;
    r.z = r.z > 0.f ? r.z : 0.01f * r.z;
    r.w = r.w > 0.f ? r.w : 0.01f * r.w;
    ((float4*)(h + (size_t)gw * NHID))[lane] = r;
}

// ------- layer-2 aggregation: fp16 sup2 gather, bias + softmax -----------
__global__ void k_agg2(const __half2* __restrict__ sup,   // [N][32] __half2
                       const float* __restrict__ bias,
                       float* __restrict__ out) {
    int gw = (blockIdx.x * blockDim.x + threadIdx.x) >> 5;
    if (gw >= N_NODES) return;
    int lane = threadIdx.x & 31;
    int beg = g_row_ptr[gw], end = g_row_ptr[gw + 1];
    float2 a0 = make_float2(0.f, 0.f);
    float2 a1 = make_float2(0.f, 0.f);
    int e = beg;
    for (; e + 2 <= end; e += 2) {
        Edge e0 = g_edges[e], e1 = g_edges[e + 1];
        float2 v0 = __half22float2(sup[(size_t)e0.s * 32 + lane]);
        float2 v1 = __half22float2(sup[(size_t)e1.s * 32 + lane]);
        a0.x += e0.w * v0.x; a0.y += e0.w * v0.y;
        a1.x += e1.w * v1.x; a1.y += e1.w * v1.y;
    }
    if (e < end) {
        Edge e0 = g_edges[e];
        float2 v0 = __half22float2(sup[(size_t)e0.s * 32 + lane]);
        a0.x += e0.w * v0.x; a0.y += e0.w * v0.y;
    }
    float2 bb = ((const float2*)bias)[lane];
    float lx = a0.x + a1.x + bb.x;
    float ly = a0.y + a1.y + bb.y;
    float m = fmaxf(lx, ly);
    #pragma unroll
    for (int o = 16; o > 0; o >>= 1)
        m = fmaxf(m, __shfl_xor_sync(0xFFFFFFFFu, m, o));
    float ex = __expf(lx - m), ey = __expf(ly - m);
    float s = ex + ey;
    #pragma unroll
    for (int o = 16; o > 0; o >>= 1)
        s += __shfl_xor_sync(0xFFFFFFFFu, s, o);
    float inv = 1.f / s;
    ((float2*)(out + (size_t)gw * NCLASS))[lane] = make_float2(ex * inv, ey * inv);
}

// ---------------- launch ----------------
extern "C" void kernel_launch(void* const* d_in, const int* in_sizes, int n_in,
                              void* d_out, int out_size) {
    const float* y    = (const float*)d_in[0];
    const void*  srcp = d_in[1];
    const void*  dstp = d_in[2];
    const float* ew   = (const float*)d_in[3];
    const float* W1   = (const float*)d_in[4];
    const float* b1   = (const float*)d_in[5];
    const float* W2   = (const float*)d_in[6];
    const float* b2   = (const float*)d_in[7];

    float* out_softmax = (float*)d_out;                              // [N, 64]
    float* out_emb     = (float*)d_out + (size_t)N_NODES * NCLASS;   // [N, 128]

    __half* sup1h; cudaGetSymbolAddress((void**)&sup1h, g_support1h);
    __half* sup2h; cudaGetSymbolAddress((void**)&sup2h, g_support2h);
    __half* b1h;
    __nv_bfloat16 *b2h, *b2l;
    cudaGetSymbolAddress((void**)&b1h, g_B1t_h);
    cudaGetSymbolAddress((void**)&b2h, g_B2t_h);
    cudaGetSymbolAddress((void**)&b2l, g_B2t_l);

    const int SMEM1 = 40960 + 20480;   // BN=128, B hi only (fp16 2-product)
    const int SMEM2 = 40960 + 20480;   // BN=64,  B hi+lo (bf16 3-product)
    static bool init_done = false;
    static cudaStream_t s2 = nullptr;
    static cudaEvent_t evFork = nullptr, evJoin = nullptr;
    if (!init_done) {
        cudaFuncSetAttribute(k_mma_gemm<NFEAT, NHID, true, true>,
                             cudaFuncAttributeMaxDynamicSharedMemorySize, SMEM1);
        cudaFuncSetAttribute(k_mma_gemm<NHID, NCLASS, false, true>,
                             cudaFuncAttributeMaxDynamicSharedMemorySize, SMEM2);
        cudaStreamCreateWithFlags(&s2, cudaStreamNonBlocking);
        cudaEventCreateWithFlags(&evFork, cudaEventDisableTiming);
        cudaEventCreateWithFlags(&evJoin, cudaEventDisableTiming);
        init_done = true;
    }

    // ---- fork: CSR build + W2 prep on side stream, hidden under GEMM1 ----
    cudaEventRecord(evFork, 0);
    cudaStreamWaitEvent(s2, evFork, 0);

    k_prepB<NHID, NCLASS><<<(NHID * NCLASS + 255) / 256, 256, 0, s2>>>(W2, b2h, b2l);
    k_detect<<<1, 1, 0, s2>>>(dstp);
    k_zero_cnt<<<(N_NODES + 255) / 256, 256, 0, s2>>>();
    k_count<<<(N_EDGES + 255) / 256, 256, 0, s2>>>(dstp);
    k_partsum<<<SCAN_BLOCKS, 1024, 0, s2>>>();
    k_scanpart<<<1, 128, 0, s2>>>();
    k_scanfinal<<<SCAN_BLOCKS, 1024, 0, s2>>>();
    k_scatter<<<(N_EDGES + 255) / 256, 256, 0, s2>>>(srcp, dstp, ew);
    cudaEventRecord(evJoin, s2);

    // ---- main stream: dense chain ----
    k_prepBh<NFEAT, NHID><<<(NFEAT * NHID + 255) / 256, 256>>>(W1, b1h);

    const int gblocks = (N_NODES + 127) / 128;
    k_mma_gemm<NFEAT, NHID, true, true><<<gblocks, 256, SMEM1>>>(
        y, b1h, b1h, sup1h, N_NODES);

    // ---- join: agg needs CSR ----
    cudaStreamWaitEvent(0, evJoin, 0);

    k_agg1<<<(N_NODES * 32 + 255) / 256, 256>>>((const __half2*)sup1h, b1,
                                                out_emb);
    k_mma_gemm<NHID, NCLASS, false, true><<<gblocks, 256, SMEM2>>>(
        out_emb, b2h, b2l, sup2h, N_NODES);
    k_agg2<<<(N_NODES * 32 + 255) / 256, 256>>>((const __half2*)sup2h, b2,
                                                out_softmax);
}